// round 2
// baseline (speedup 1.0000x reference)
#include <cuda_runtime.h>
#include <math.h>

// Problem constants (hard-coded in the reference module)
#define T_STEPS 30
#define ISZ     100
#define HSZ     256
#define NSEQ    5120          // 512 * 10
#define NBATCH  512

// State scratch (allocation-free rule: __device__ globals)
// h: ping-pong [parity][dir*NSEQ*HSZ + ...], c: [dir*NSEQ*HSZ + ...]
__device__ float g_h[2][2 * NSEQ * HSZ];
__device__ float g_c[2 * NSEQ * HSZ];

__global__ void init_state(const float* __restrict__ h0, const float* __restrict__ c0) {
    int i = blockIdx.x * blockDim.x + threadIdx.x;
    const int tot = 2 * NSEQ * HSZ;
    if (i < tot) {
        g_h[0][i] = h0[i];
        g_c[i]    = c0[i];
    }
}

__device__ __forceinline__ float sigm(float v) { return 1.0f / (1.0f + expf(-v)); }

// One LSTM timestep, both directions (blockIdx.z = dir).
// Each block: 64 batch rows x 64 hidden cols, computing ALL FOUR gate tiles
// (column offsets g*256) so the cell update is thread-local.
// GEMM K = 100 (input, from x) + 256 (hidden, from h_in), fp32.
__global__ __launch_bounds__(256) void lstm_step(
    const float* __restrict__ x,
    const float* __restrict__ Wih_f, const float* __restrict__ Whh_f,
    const float* __restrict__ bih_f, const float* __restrict__ bhh_f,
    const float* __restrict__ Wih_b, const float* __restrict__ Whh_b,
    const float* __restrict__ bih_b, const float* __restrict__ bhh_b,
    int s)
{
    const int d = blockIdx.z;
    const float* __restrict__ Wih = d ? Wih_b : Wih_f;
    const float* __restrict__ Whh = d ? Whh_b : Whh_f;
    const float* __restrict__ bih = d ? bih_b : bih_f;
    const float* __restrict__ bhh = d ? bhh_b : bhh_f;
    const int t = d ? (T_STEPS - 1 - s) : s;

    const float* __restrict__ h_in  = g_h[s & 1]       + d * (NSEQ * HSZ);
    float*       __restrict__ h_out = g_h[(s + 1) & 1] + d * (NSEQ * HSZ);
    float*       __restrict__ c_st  = g_c              + d * (NSEQ * HSZ);

    const int hbase = blockIdx.x * 64;   // hidden-col tile base (0..192)
    const int n0    = blockIdx.y * 64;   // batch-row tile base
    const int tid   = threadIdx.x;
    const int tx    = tid & 15;          // 16 col-threads (4 cols each)
    const int ty    = tid >> 4;          // 16 row-threads (4 rows each)

    __shared__ float As[64][17];         // [row][k], pad 17 -> conflict-free
    __shared__ float Bs[4][16][68];      // [gate][k][col], pad 68 (float4-aligned)

    float acc[4][4][4];                  // [gate][row][col]
#pragma unroll
    for (int g = 0; g < 4; g++)
#pragma unroll
        for (int r = 0; r < 4; r++)
#pragma unroll
            for (int c = 0; c < 4; c++) acc[g][r][c] = 0.0f;

    // ---------------- Phase 1: input contribution, K = 100 ----------------
    for (int kb = 0; kb < ISZ; kb += 16) {
        // load A tile: x[n, t, k]  (64 rows x 16 k)
#pragma unroll
        for (int j = 0; j < 4; j++) {
            int i   = tid + j * 256;
            int row = i >> 4;
            int k   = i & 15;
            int kg  = kb + k;
            As[row][k] = (kg < ISZ) ? x[(size_t)(n0 + row) * (T_STEPS * ISZ) + t * ISZ + kg] : 0.0f;
        }
        // load B tiles: Wih[(g*256 + hbase + col) * 100 + k] for 4 gates
#pragma unroll
        for (int j = 0; j < 16; j++) {
            int i   = tid + j * 256;
            int g   = i >> 10;
            int rem = i & 1023;
            int col = rem >> 4;
            int k   = rem & 15;
            int kg  = kb + k;
            Bs[g][k][col] = (kg < ISZ) ? Wih[(size_t)(g * HSZ + hbase + col) * ISZ + kg] : 0.0f;
        }
        __syncthreads();
#pragma unroll
        for (int k = 0; k < 16; k++) {
            float a0 = As[ty * 4 + 0][k];
            float a1 = As[ty * 4 + 1][k];
            float a2 = As[ty * 4 + 2][k];
            float a3 = As[ty * 4 + 3][k];
#pragma unroll
            for (int g = 0; g < 4; g++) {
                float4 b = *(const float4*)&Bs[g][k][tx * 4];
                acc[g][0][0] += a0 * b.x; acc[g][0][1] += a0 * b.y; acc[g][0][2] += a0 * b.z; acc[g][0][3] += a0 * b.w;
                acc[g][1][0] += a1 * b.x; acc[g][1][1] += a1 * b.y; acc[g][1][2] += a1 * b.z; acc[g][1][3] += a1 * b.w;
                acc[g][2][0] += a2 * b.x; acc[g][2][1] += a2 * b.y; acc[g][2][2] += a2 * b.z; acc[g][2][3] += a2 * b.w;
                acc[g][3][0] += a3 * b.x; acc[g][3][1] += a3 * b.y; acc[g][3][2] += a3 * b.z; acc[g][3][3] += a3 * b.w;
            }
        }
        __syncthreads();
    }

    // ---------------- Phase 2: hidden contribution, K = 256 ----------------
    for (int kb = 0; kb < HSZ; kb += 16) {
#pragma unroll
        for (int j = 0; j < 4; j++) {
            int i   = tid + j * 256;
            int row = i >> 4;
            int k   = i & 15;
            As[row][k] = h_in[(size_t)(n0 + row) * HSZ + kb + k];
        }
#pragma unroll
        for (int j = 0; j < 16; j++) {
            int i   = tid + j * 256;
            int g   = i >> 10;
            int rem = i & 1023;
            int col = rem >> 4;
            int k   = rem & 15;
            Bs[g][k][col] = Whh[(size_t)(g * HSZ + hbase + col) * HSZ + kb + k];
        }
        __syncthreads();
#pragma unroll
        for (int k = 0; k < 16; k++) {
            float a0 = As[ty * 4 + 0][k];
            float a1 = As[ty * 4 + 1][k];
            float a2 = As[ty * 4 + 2][k];
            float a3 = As[ty * 4 + 3][k];
#pragma unroll
            for (int g = 0; g < 4; g++) {
                float4 b = *(const float4*)&Bs[g][k][tx * 4];
                acc[g][0][0] += a0 * b.x; acc[g][0][1] += a0 * b.y; acc[g][0][2] += a0 * b.z; acc[g][0][3] += a0 * b.w;
                acc[g][1][0] += a1 * b.x; acc[g][1][1] += a1 * b.y; acc[g][1][2] += a1 * b.z; acc[g][1][3] += a1 * b.w;
                acc[g][2][0] += a2 * b.x; acc[g][2][1] += a2 * b.y; acc[g][2][2] += a2 * b.z; acc[g][2][3] += a2 * b.w;
                acc[g][3][0] += a3 * b.x; acc[g][3][1] += a3 * b.y; acc[g][3][2] += a3 * b.z; acc[g][3][3] += a3 * b.w;
            }
        }
        __syncthreads();
    }

    // ---------------- Epilogue: bias + LSTM cell, write h/c ----------------
#pragma unroll
    for (int c = 0; c < 4; c++) {
        const int col = hbase + tx * 4 + c;
        const float bi = bih[0 * HSZ + col] + bhh[0 * HSZ + col];
        const float bf = bih[1 * HSZ + col] + bhh[1 * HSZ + col];
        const float bg = bih[2 * HSZ + col] + bhh[2 * HSZ + col];
        const float bo = bih[3 * HSZ + col] + bhh[3 * HSZ + col];
#pragma unroll
        for (int r = 0; r < 4; r++) {
            const int n   = n0 + ty * 4 + r;
            const size_t idx = (size_t)n * HSZ + col;
            const float iv = sigm(acc[0][r][c] + bi);
            const float fv = sigm(acc[1][r][c] + bf);
            const float gv = tanhf(acc[2][r][c] + bg);
            const float ov = sigm(acc[3][r][c] + bo);
            const float cn = fv * c_st[idx] + iv * gv;
            c_st[idx]  = cn;
            h_out[idx] = ov * tanhf(cn);
        }
    }
}

// Head: x_fea assembly + Linear(2560->64) -> Linear(64->5) -> Softmax.
// One block per batch element b. Final h lives in g_h[0] (30 steps, even).
__global__ __launch_bounds__(256) void head_kernel(
    const float* __restrict__ W1, const float* __restrict__ b1,
    const float* __restrict__ W2, const float* __restrict__ b2,
    float* __restrict__ out)
{
    __shared__ float fea[2560];
    __shared__ float zp[4][64];
    __shared__ float zz[64];
    __shared__ float lg[5];

    const int b   = blockIdx.x;
    const int tid = threadIdx.x;
    const float* __restrict__ hF = g_h[0];
    const float* __restrict__ hB = g_h[0] + NSEQ * HSZ;

    // x_fea[b, slot, m] = m<128 ? hF[b*10+slot, m] : hB[b*10+slot, m]
    for (int i = tid; i < 2560; i += 256) {
        const int slot = i >> 8;
        const int m    = i & 255;
        const int n    = b * 10 + slot;
        const float v  = (m < 128) ? hF[(size_t)n * HSZ + m] : hB[(size_t)n * HSZ + m];
        fea[i] = v;
        out[2560 + (size_t)b * 2560 + i] = v;   // x_fea after y_pred (tuple order)
    }
    __syncthreads();

    // z = fea @ W1^T + b1  (64 outputs, 4-way K split)
    const int j = tid & 63;
    const int p = tid >> 6;
    float sum = 0.0f;
    const int k0 = p * 640;
    for (int k = k0; k < k0 + 640; k++) sum += fea[k] * W1[(size_t)j * 2560 + k];
    zp[p][j] = sum;
    __syncthreads();
    if (tid < 64) zz[tid] = zp[0][tid] + zp[1][tid] + zp[2][tid] + zp[3][tid] + b1[tid];
    __syncthreads();

    if (tid < 5) {
        float s = b2[tid];
        for (int k = 0; k < 64; k++) s += zz[k] * W2[tid * 64 + k];
        lg[tid] = s;
    }
    __syncthreads();
    if (tid == 0) {
        float m = lg[0];
        for (int k = 1; k < 5; k++) m = fmaxf(m, lg[k]);
        float e[5], se = 0.0f;
        for (int k = 0; k < 5; k++) { e[k] = expf(lg[k] - m); se += e[k]; }
        for (int k = 0; k < 5; k++) out[(size_t)b * 5 + k] = e[k] / se;
    }
}

extern "C" void kernel_launch(void* const* d_in, const int* in_sizes, int n_in,
                              void* d_out, int out_size) {
    const float* x     = (const float*)d_in[0];
    const float* h0    = (const float*)d_in[1];
    const float* c0    = (const float*)d_in[2];
    const float* Wih_f = (const float*)d_in[3];
    const float* Whh_f = (const float*)d_in[4];
    const float* bih_f = (const float*)d_in[5];
    const float* bhh_f = (const float*)d_in[6];
    const float* Wih_b = (const float*)d_in[7];
    const float* Whh_b = (const float*)d_in[8];
    const float* bih_b = (const float*)d_in[9];
    const float* bhh_b = (const float*)d_in[10];
    const float* W1    = (const float*)d_in[11];
    const float* b1    = (const float*)d_in[12];
    const float* W2    = (const float*)d_in[13];
    const float* b2    = (const float*)d_in[14];
    float* out = (float*)d_out;

    init_state<<<(2 * NSEQ * HSZ + 255) / 256, 256>>>(h0, c0);

    dim3 grid(HSZ / 64, NSEQ / 64, 2);   // (4, 80, 2)
    for (int s = 0; s < T_STEPS; s++) {
        lstm_step<<<grid, 256>>>(x, Wih_f, Whh_f, bih_f, bhh_f,
                                 Wih_b, Whh_b, bih_b, bhh_b, s);
    }

    head_kernel<<<NBATCH, 256>>>(W1, b1, W2, b2, out);
}

// round 4
// speedup vs baseline: 2.1062x; 2.1062x over previous
#include <cuda_runtime.h>
#include <cuda_bf16.h>
#include <cstdint>
#include <cstring>
#include <math.h>

// ---------------- problem constants ----------------
#define T_STEPS 30
#define ISZ     100
#define HSZ     256
#define NSEQ    5120
#define NBATCH  512
#define NCH     12            // k-chunks of 32: 4 (x pad 128) + 8 (h 256)

// ---------------- device scratch (allocation-free rule) ----------------
// bf16 hi/lo split images, row-major k-contiguous (unswizzled; swizzle applied at smem store)
__device__ __nv_bfloat16 g_Ax[T_STEPS][40][2][128][128];   // [t][mt][img][row][k]  x, k padded 100->128
__device__ __nv_bfloat16 g_Ah[2][2][40][2][128][256];      // [par][dir][mt][img][row][k]
__device__ __nv_bfloat16 g_Bx[2][8][2][128][128];          // [dir][nt][img][c'][k]  Wih, gate-interleaved
__device__ __nv_bfloat16 g_Bh[2][8][2][128][256];          // [dir][nt][img][c'][k]  Whh
__device__ float g_bias[2][1024];                           // [dir][c'=h*4+g]
__device__ float g_c[2 * NSEQ * HSZ];
__device__ float g_h[2 * NSEQ * HSZ];                       // finals only (s==29)

// ---------------- helpers ----------------
__device__ __forceinline__ uint32_t smem_u32(const void* p) {
    uint32_t a;
    asm("{ .reg .u64 t; cvta.to.shared.u64 t, %1; cvt.u32.u64 %0, t; }" : "=r"(a) : "l"(p));
    return a;
}
__device__ __forceinline__ void cpa16(uint32_t dst, const void* src) {
    asm volatile("cp.async.cg.shared.global [%0], [%1], 16;" :: "r"(dst), "l"(src));
}
#define CP_COMMIT() asm volatile("cp.async.commit_group;" ::: "memory")
#define CP_WAIT1()  asm volatile("cp.async.wait_group 1;" ::: "memory")
#define CP_WAIT0()  asm volatile("cp.async.wait_group 0;" ::: "memory")

__device__ __forceinline__ void ldm_x4(uint32_t* r, uint32_t addr) {
    asm volatile("ldmatrix.sync.aligned.m8n8.x4.shared.b16 {%0,%1,%2,%3}, [%4];"
                 : "=r"(r[0]), "=r"(r[1]), "=r"(r[2]), "=r"(r[3]) : "r"(addr));
}
__device__ __forceinline__ void mma16816(float* d, const uint32_t* a, uint32_t b0, uint32_t b1) {
    asm volatile(
        "mma.sync.aligned.m16n8k16.row.col.f32.bf16.bf16.f32 "
        "{%0,%1,%2,%3}, {%4,%5,%6,%7}, {%8,%9}, {%0,%1,%2,%3};"
        : "+f"(d[0]), "+f"(d[1]), "+f"(d[2]), "+f"(d[3])
        : "r"(a[0]), "r"(a[1]), "r"(a[2]), "r"(a[3]), "r"(b0), "r"(b1));
}
// 64B-row smem tile swizzle: 16B-chunk permutation, conflict-free for ldmatrix 8-row phases
__device__ __forceinline__ uint32_t swz_off(int row, int chunk) {
    int c = chunk ^ (row & 3) ^ ((row >> 2) & 1);
    return (uint32_t)(row * 64 + c * 16);
}
__device__ __forceinline__ float sigm(float v) { return 1.0f / (1.0f + expf(-v)); }
__device__ __forceinline__ void split_bf(float v, uint16_t& hi_b, uint16_t& lo_b) {
    __nv_bfloat16 h = __float2bfloat16(v);
    float hf = __bfloat162float(h);
    memcpy(&hi_b, &h, 2);
    __nv_bfloat16 l = __float2bfloat16(v - hf);
    memcpy(&lo_b, &l, 2);
}

// ---------------- prepack kernels ----------------
__global__ void prepack_x(const float* __restrict__ x) {
    int idx = blockIdx.x * blockDim.x + threadIdx.x;
    const int TOT = T_STEPS * NSEQ * 128;
    if (idx >= TOT) return;
    int k = idx & 127;
    int n = (idx >> 7) % NSEQ;
    int t = idx / (NSEQ * 128);
    float v = (k < ISZ) ? x[((size_t)n * T_STEPS + t) * ISZ + k] : 0.0f;
    uint16_t hb, lb; split_bf(v, hb, lb);
    int mt = n >> 7, m = n & 127;
    memcpy(&g_Ax[t][mt][0][m][k], &hb, 2);
    memcpy(&g_Ax[t][mt][1][m][k], &lb, 2);
}
__global__ void prepack_h0(const float* __restrict__ h0) {
    int idx = blockIdx.x * blockDim.x + threadIdx.x;
    const int TOT = 2 * NSEQ * HSZ;
    if (idx >= TOT) return;
    int k = idx & 255;
    int n = (idx >> 8) % NSEQ;
    int d = idx / (NSEQ * HSZ);
    float v = h0[idx];
    uint16_t hb, lb; split_bf(v, hb, lb);
    int mt = n >> 7, m = n & 127;
    memcpy(&g_Ah[0][d][mt][0][m][k], &hb, 2);
    memcpy(&g_Ah[0][d][mt][1][m][k], &lb, 2);
}
__global__ void prepack_W(const float* __restrict__ Wih_f, const float* __restrict__ Whh_f,
                          const float* __restrict__ Wih_b, const float* __restrict__ Whh_b) {
    int idx = blockIdx.x * blockDim.x + threadIdx.x;
    const int TOT = 2 * 8 * 128 * 384;
    if (idx >= TOT) return;
    int k = idx % 384;
    int rest = idx / 384;
    int c = rest & 127;
    rest >>= 7;
    int nt = rest & 7;
    int dir = rest >> 3;
    const float* Wih = dir ? Wih_b : Wih_f;
    const float* Whh = dir ? Whh_b : Whh_f;
    int hg = nt * 32 + (c >> 2);
    int g = c & 3;
    int row = g * HSZ + hg;
    uint16_t hb, lb;
    if (k < 128) {
        float v = (k < ISZ) ? Wih[(size_t)row * ISZ + k] : 0.0f;
        split_bf(v, hb, lb);
        memcpy(&g_Bx[dir][nt][0][c][k], &hb, 2);
        memcpy(&g_Bx[dir][nt][1][c][k], &lb, 2);
    } else {
        float v = Whh[(size_t)row * HSZ + (k - 128)];
        split_bf(v, hb, lb);
        memcpy(&g_Bh[dir][nt][0][c][k - 128], &hb, 2);
        memcpy(&g_Bh[dir][nt][1][c][k - 128], &lb, 2);
    }
}
__global__ void prepack_bias(const float* __restrict__ bih_f, const float* __restrict__ bhh_f,
                             const float* __restrict__ bih_b, const float* __restrict__ bhh_b) {
    int idx = blockIdx.x * blockDim.x + threadIdx.x;
    if (idx >= 2048) return;
    int c = idx & 1023, dir = idx >> 10;
    int h = c >> 2, g = c & 3;
    int row = g * HSZ + h;
    g_bias[dir][c] = dir ? (bih_b[row] + bhh_b[row]) : (bih_f[row] + bhh_f[row]);
}
__global__ void init_c(const float* __restrict__ c0) {
    int i = blockIdx.x * blockDim.x + threadIdx.x;
    if (i < 2 * NSEQ * HSZ) g_c[i] = c0[i];
}

// ---------------- mma.sync LSTM step ----------------
// smem: [0..511] bias (128 f32) | [512..66047] 2 stages x 32KB | epilogue C overlays at 512
#define SM_BIAS  0
#define SM_STG   512
#define SM_C     512
#define SM_TOTAL (512 + 128 * 132 * 4)   // 68096

__global__ void __launch_bounds__(256, 1) lstm_step_mma(int s) {
    extern __shared__ __align__(16) unsigned char smem[];
    const uint32_t sbase = smem_u32(smem);
    const int tid  = threadIdx.x;
    const int wid  = tid >> 5;
    const int lane = tid & 31;
    const int wm   = wid & 3;   // warp row  (32 rows)
    const int wn   = wid >> 2;  // warp col  (64 cols)
    const int nt   = blockIdx.x;
    const int mt   = blockIdx.y;
    const int dir  = blockIdx.z;
    const int t    = dir ? (T_STEPS - 1 - s) : s;
    const int par  = s & 1;

    float* bias_sm = (float*)(smem + SM_BIAS);
    if (tid < 128) bias_sm[tid] = g_bias[dir][nt * 128 + tid];

    auto load_chunk = [&](int ck, int st) {
        const uint32_t stg = sbase + SM_STG + st * 32768;
        const __nv_bfloat16 *Aptr, *Bptr;
        int astr, bstr;
        if (ck < 4) {
            Aptr = &g_Ax[t][mt][0][0][0] + ck * 32;       astr = 128;
            Bptr = &g_Bx[dir][nt][0][0][0] + ck * 32;     bstr = 128;
        } else {
            Aptr = &g_Ah[par][dir][mt][0][0][0] + (ck - 4) * 32;  astr = 256;
            Bptr = &g_Bh[dir][nt][0][0][0] + (ck - 4) * 32;       bstr = 256;
        }
#pragma unroll
        for (int j = 0; j < 4; j++) {
            int id  = tid + j * 256;
            int ch  = id & 3;
            int row = (id >> 2) & 127;
            int img = id >> 9;
            cpa16(stg + img * 8192 + swz_off(row, ch),
                  Aptr + (size_t)img * 128 * astr + (size_t)row * astr + ch * 8);
        }
#pragma unroll
        for (int j = 0; j < 4; j++) {
            int id  = tid + j * 256;
            int ch  = id & 3;
            int row = (id >> 2) & 127;
            int img = id >> 9;
            cpa16(stg + 16384 + img * 8192 + swz_off(row, ch),
                  Bptr + (size_t)img * 128 * bstr + (size_t)row * bstr + ch * 8);
        }
    };

    float acc[2][8][4];
#pragma unroll
    for (int mi = 0; mi < 2; mi++)
#pragma unroll
        for (int nj = 0; nj < 8; nj++)
#pragma unroll
            for (int e = 0; e < 4; e++) acc[mi][nj][e] = 0.0f;

    load_chunk(0, 0);
    CP_COMMIT();

    for (int ck = 0; ck < NCH; ck++) {
        if (ck + 1 < NCH) {
            load_chunk(ck + 1, (ck + 1) & 1);
            CP_COMMIT();
            CP_WAIT1();
        } else {
            CP_WAIT0();
        }
        __syncthreads();

        const uint32_t stg = sbase + SM_STG + (ck & 1) * 32768;
        const uint32_t Ab0 = stg, Ab1 = stg + 8192;
        const uint32_t Bb0 = stg + 16384, Bb1 = stg + 24576;
#pragma unroll
        for (int kh = 0; kh < 2; kh++) {
            const int ac = kh * 2 + (lane >> 4);
            uint32_t ah[2][4], al[2][4], bh[4][4], bl[4][4];
#pragma unroll
            for (int fi = 0; fi < 2; fi++) {
                const int row = wm * 32 + fi * 16 + (lane & 15);
                const uint32_t off = swz_off(row, ac);
                ldm_x4(ah[fi], Ab0 + off);
                ldm_x4(al[fi], Ab1 + off);
            }
#pragma unroll
            for (int gp = 0; gp < 4; gp++) {
                const int col = wn * 64 + gp * 16 + (lane & 15);
                const uint32_t off = swz_off(col, ac);
                ldm_x4(bh[gp], Bb0 + off);
                ldm_x4(bl[gp], Bb1 + off);
            }
#pragma unroll
            for (int mi = 0; mi < 2; mi++)
#pragma unroll
                for (int gp = 0; gp < 4; gp++)
#pragma unroll
                    for (int sub = 0; sub < 2; sub++) {
                        float* d = acc[mi][gp * 2 + sub];
                        mma16816(d, ah[mi], bh[gp][sub], bh[gp][sub + 2]);
                        mma16816(d, ah[mi], bl[gp][sub], bl[gp][sub + 2]);
                        mma16816(d, al[mi], bh[gp][sub], bh[gp][sub + 2]);
                    }
        }
        __syncthreads();
    }

    // ---------------- epilogue: preactivations -> smem -> LSTM cell ----------------
    float* Csm = (float*)(smem + SM_C);
#pragma unroll
    for (int mi = 0; mi < 2; mi++)
#pragma unroll
        for (int nj = 0; nj < 8; nj++) {
            const int r = wm * 32 + mi * 16 + (lane >> 2);
            const int c = wn * 64 + nj * 8 + (lane & 3) * 2;
            float* p = Csm + r * 132 + c;
            p[0] = acc[mi][nj][0];
            p[1] = acc[mi][nj][1];
            float* q = Csm + (r + 8) * 132 + c;
            q[0] = acc[mi][nj][2];
            q[1] = acc[mi][nj][3];
        }
    __syncthreads();

    const int n_l   = tid >> 1;
    const int halfh = tid & 1;
    const int n     = mt * 128 + n_l;
    const size_t cbase = (size_t)dir * NSEQ * HSZ + (size_t)n * HSZ;
    uint16_t hb[16], lb[16];
#pragma unroll
    for (int i = 0; i < 16; i++) {
        const int h_l = halfh * 16 + i;
        const float4 gt = *(const float4*)&Csm[n_l * 132 + h_l * 4];
        const float iv = sigm(gt.x + bias_sm[h_l * 4 + 0]);
        const float fv = sigm(gt.y + bias_sm[h_l * 4 + 1]);
        const float gv = tanhf(gt.z + bias_sm[h_l * 4 + 2]);
        const float ov = sigm(gt.w + bias_sm[h_l * 4 + 3]);
        const size_t ci = cbase + nt * 32 + h_l;
        const float cn = fv * g_c[ci] + iv * gv;
        g_c[ci] = cn;
        const float hv = ov * tanhf(cn);
        if (s == T_STEPS - 1) g_h[ci] = hv;
        split_bf(hv, hb[i], lb[i]);
    }
    // pack next-step h (32B per image per thread, contiguous)
    {
        const int kcol = nt * 32 + halfh * 16;
        uint4 u0, u1;
        uint32_t* w;
        w = (uint32_t*)&u0;
#pragma unroll
        for (int q = 0; q < 4; q++) w[q] = (uint32_t)hb[q * 2] | ((uint32_t)hb[q * 2 + 1] << 16);
        w = (uint32_t*)&u1;
#pragma unroll
        for (int q = 0; q < 4; q++) w[q] = (uint32_t)hb[8 + q * 2] | ((uint32_t)hb[8 + q * 2 + 1] << 16);
        *(uint4*)&g_Ah[par ^ 1][dir][mt][0][n_l][kcol]     = u0;
        *(uint4*)&g_Ah[par ^ 1][dir][mt][0][n_l][kcol + 8] = u1;
        w = (uint32_t*)&u0;
#pragma unroll
        for (int q = 0; q < 4; q++) w[q] = (uint32_t)lb[q * 2] | ((uint32_t)lb[q * 2 + 1] << 16);
        w = (uint32_t*)&u1;
#pragma unroll
        for (int q = 0; q < 4; q++) w[q] = (uint32_t)lb[8 + q * 2] | ((uint32_t)lb[8 + q * 2 + 1] << 16);
        *(uint4*)&g_Ah[par ^ 1][dir][mt][1][n_l][kcol]     = u0;
        *(uint4*)&g_Ah[par ^ 1][dir][mt][1][n_l][kcol + 8] = u1;
    }
}

// ---------------- head ----------------
__global__ __launch_bounds__(256) void head_kernel(
    const float* __restrict__ W1, const float* __restrict__ b1,
    const float* __restrict__ W2, const float* __restrict__ b2,
    float* __restrict__ out)
{
    __shared__ float fea[2560];
    __shared__ float zp[4][64];
    __shared__ float zz[64];
    __shared__ float lg[5];

    const int b = blockIdx.x;
    const int tid = threadIdx.x;
    const float* __restrict__ hF = g_h;
    const float* __restrict__ hB = g_h + NSEQ * HSZ;

    for (int i = tid; i < 2560; i += 256) {
        const int slot = i >> 8;
        const int mcol = i & 255;
        const int n = b * 10 + slot;
        const float v = (mcol < 128) ? hF[(size_t)n * HSZ + mcol] : hB[(size_t)n * HSZ + mcol];
        fea[i] = v;
        out[2560 + (size_t)b * 2560 + i] = v;
    }
    __syncthreads();

    const int j = tid & 63;
    const int p = tid >> 6;
    float sum = 0.0f;
    const int k0 = p * 640;
    for (int k = k0; k < k0 + 640; k++) sum += fea[k] * W1[(size_t)j * 2560 + k];
    zp[p][j] = sum;
    __syncthreads();
    if (tid < 64) zz[tid] = zp[0][tid] + zp[1][tid] + zp[2][tid] + zp[3][tid] + b1[tid];
    __syncthreads();

    if (tid < 5) {
        float ss = b2[tid];
        for (int k = 0; k < 64; k++) ss += zz[k] * W2[tid * 64 + k];
        lg[tid] = ss;
    }
    __syncthreads();
    if (tid == 0) {
        float mx = lg[0];
        for (int k = 1; k < 5; k++) mx = fmaxf(mx, lg[k]);
        float e[5], se = 0.0f;
        for (int k = 0; k < 5; k++) { e[k] = expf(lg[k] - mx); se += e[k]; }
        for (int k = 0; k < 5; k++) out[(size_t)b * 5 + k] = e[k] / se;
    }
}

extern "C" void kernel_launch(void* const* d_in, const int* in_sizes, int n_in,
                              void* d_out, int out_size) {
    const float* x     = (const float*)d_in[0];
    const float* h0    = (const float*)d_in[1];
    const float* c0    = (const float*)d_in[2];
    const float* Wih_f = (const float*)d_in[3];
    const float* Whh_f = (const float*)d_in[4];
    const float* bih_f = (const float*)d_in[5];
    const float* bhh_f = (const float*)d_in[6];
    const float* Wih_b = (const float*)d_in[7];
    const float* Whh_b = (const float*)d_in[8];
    const float* bih_b = (const float*)d_in[9];
    const float* bhh_b = (const float*)d_in[10];
    const float* W1    = (const float*)d_in[11];
    const float* b1    = (const float*)d_in[12];
    const float* W2    = (const float*)d_in[13];
    const float* b2    = (const float*)d_in[14];
    float* out = (float*)d_out;

    cudaFuncSetAttribute(lstm_step_mma, cudaFuncAttributeMaxDynamicSharedMemorySize, SM_TOTAL);

    prepack_bias<<<8, 256>>>(bih_f, bhh_f, bih_b, bhh_b);
    prepack_W<<<(2 * 8 * 128 * 384 + 255) / 256, 256>>>(Wih_f, Whh_f, Wih_b, Whh_b);
    prepack_x<<<(T_STEPS * NSEQ * 128 + 255) / 256, 256>>>(x);
    prepack_h0<<<(2 * NSEQ * HSZ + 255) / 256, 256>>>(h0);
    init_c<<<(2 * NSEQ * HSZ + 255) / 256, 256>>>(c0);

    dim3 grid(8, 40, 2);
    for (int s = 0; s < T_STEPS; s++) {
        lstm_step_mma<<<grid, 256, SM_TOTAL>>>(s);
    }
    head_kernel<<<NBATCH, 256>>>(W1, b1, W2, b2, out);
}

// round 5
// speedup vs baseline: 2.1191x; 1.0061x over previous
#include <cuda_runtime.h>
#include <cuda_bf16.h>
#include <cstdint>
#include <cstring>
#include <math.h>

// ---------------- problem constants ----------------
#define T_STEPS 30
#define ISZ     100
#define HSZ     256
#define NSEQ    5120
#define NBATCH  512

// ---------------- device scratch (allocation-free rule) ----------------
// bf16 hi/lo split images, row-major k-contiguous (swizzle applied at smem store)
__device__ __nv_bfloat16 g_Ax[T_STEPS][40][2][128][128];   // [t][mt][img][row][k]  x, k padded 100->128
__device__ __nv_bfloat16 g_Ah[2][2][40][2][128][256];      // [par][dir][mt][img][row][k]
__device__ __nv_bfloat16 g_Bx[2][8][2][128][128];          // [dir][nt][img][c'][k]  Wih, gate-interleaved
__device__ __nv_bfloat16 g_Bh[2][8][2][128][256];          // [dir][nt][img][c'][k]  Whh
__device__ float g_bias[2][1024];                           // [dir][c'=h*4+g]
__device__ float g_c[2 * NSEQ * HSZ];
__device__ float g_h[2 * NSEQ * HSZ];                       // finals only (s==29)
// precomputed input-gate contributions (+bias), fp32: [dir][t][mt][row 128][c' 1024]
__device__ float g_xg[(size_t)2 * T_STEPS * 40 * 128 * 1024];

// ---------------- helpers ----------------
__device__ __forceinline__ uint32_t smem_u32(const void* p) {
    uint32_t a;
    asm("{ .reg .u64 t; cvta.to.shared.u64 t, %1; cvt.u32.u64 %0, t; }" : "=r"(a) : "l"(p));
    return a;
}
__device__ __forceinline__ void cpa16(uint32_t dst, const void* src) {
    asm volatile("cp.async.cg.shared.global [%0], [%1], 16;" :: "r"(dst), "l"(src));
}
#define CP_COMMIT() asm volatile("cp.async.commit_group;" ::: "memory")
#define CP_WAIT1()  asm volatile("cp.async.wait_group 1;" ::: "memory")
#define CP_WAIT0()  asm volatile("cp.async.wait_group 0;" ::: "memory")

__device__ __forceinline__ void ldm_x4(uint32_t* r, uint32_t addr) {
    asm volatile("ldmatrix.sync.aligned.m8n8.x4.shared.b16 {%0,%1,%2,%3}, [%4];"
                 : "=r"(r[0]), "=r"(r[1]), "=r"(r[2]), "=r"(r[3]) : "r"(addr));
}
__device__ __forceinline__ void mma16816(float* d, const uint32_t* a, uint32_t b0, uint32_t b1) {
    asm volatile(
        "mma.sync.aligned.m16n8k16.row.col.f32.bf16.bf16.f32 "
        "{%0,%1,%2,%3}, {%4,%5,%6,%7}, {%8,%9}, {%0,%1,%2,%3};"
        : "+f"(d[0]), "+f"(d[1]), "+f"(d[2]), "+f"(d[3])
        : "r"(a[0]), "r"(a[1]), "r"(a[2]), "r"(a[3]), "r"(b0), "r"(b1));
}
// 128B-row smem swizzle: 16B-chunk index XOR (row & 7); conflict-free ldmatrix phases
__device__ __forceinline__ uint32_t swz128(int row, int ch) {
    return (uint32_t)(row * 128 + ((ch ^ (row & 7)) << 4));
}
// fast sigmoid / tanh via MUFU ex2 + rcp (rel err ~1e-6)
__device__ __forceinline__ float fsigm(float x) {
    float e;
    asm("ex2.approx.f32 %0, %1;" : "=f"(e) : "f"(x * -1.4426950408889634f));
    float r;
    asm("rcp.approx.f32 %0, %1;" : "=f"(r) : "f"(1.0f + e));
    return r;
}
__device__ __forceinline__ float ftanh(float x) { return fmaf(2.0f, fsigm(2.0f * x), -1.0f); }

__device__ __forceinline__ void split_bf(float v, uint16_t& hi_b, uint16_t& lo_b) {
    __nv_bfloat16 h = __float2bfloat16(v);
    float hf = __bfloat162float(h);
    memcpy(&hi_b, &h, 2);
    __nv_bfloat16 l = __float2bfloat16(v - hf);
    memcpy(&lo_b, &l, 2);
}

// ---------------- prepack kernels ----------------
__global__ void prepack_bias(const float* __restrict__ bih_f, const float* __restrict__ bhh_f,
                             const float* __restrict__ bih_b, const float* __restrict__ bhh_b) {
    int idx = blockIdx.x * blockDim.x + threadIdx.x;
    if (idx >= 2048) return;
    int c = idx & 1023, dir = idx >> 10;
    int h = c >> 2, g = c & 3;
    int row = g * HSZ + h;
    g_bias[dir][c] = dir ? (bih_b[row] + bhh_b[row]) : (bih_f[row] + bhh_f[row]);
}
__global__ void prepack_W(const float* __restrict__ Wih_f, const float* __restrict__ Whh_f,
                          const float* __restrict__ Wih_b, const float* __restrict__ Whh_b) {
    int idx = blockIdx.x * blockDim.x + threadIdx.x;
    const int TOT = 2 * 8 * 128 * 384;
    if (idx >= TOT) return;
    int k = idx % 384;
    int rest = idx / 384;
    int c = rest & 127;
    rest >>= 7;
    int nt = rest & 7;
    int dir = rest >> 3;
    const float* Wih = dir ? Wih_b : Wih_f;
    const float* Whh = dir ? Whh_b : Whh_f;
    int hg = nt * 32 + (c >> 2);
    int g = c & 3;
    int row = g * HSZ + hg;
    uint16_t hb, lb;
    if (k < 128) {
        float v = (k < ISZ) ? Wih[(size_t)row * ISZ + k] : 0.0f;
        split_bf(v, hb, lb);
        memcpy(&g_Bx[dir][nt][0][c][k], &hb, 2);
        memcpy(&g_Bx[dir][nt][1][c][k], &lb, 2);
    } else {
        float v = Whh[(size_t)row * HSZ + (k - 128)];
        split_bf(v, hb, lb);
        memcpy(&g_Bh[dir][nt][0][c][k - 128], &hb, 2);
        memcpy(&g_Bh[dir][nt][1][c][k - 128], &lb, 2);
    }
}
__global__ void prepack_x(const float* __restrict__ x) {
    int idx = blockIdx.x * blockDim.x + threadIdx.x;
    const int TOT = T_STEPS * NSEQ * 128;
    if (idx >= TOT) return;
    int k = idx & 127;
    int n = (idx >> 7) % NSEQ;
    int t = idx / (NSEQ * 128);
    float v = (k < ISZ) ? x[((size_t)n * T_STEPS + t) * ISZ + k] : 0.0f;
    uint16_t hb, lb; split_bf(v, hb, lb);
    int mt = n >> 7, m = n & 127;
    memcpy(&g_Ax[t][mt][0][m][k], &hb, 2);
    memcpy(&g_Ax[t][mt][1][m][k], &lb, 2);
}
// merged: c0 copy + h0 bf16 pack
__global__ void prepack_h0c0(const float* __restrict__ h0, const float* __restrict__ c0) {
    int idx = blockIdx.x * blockDim.x + threadIdx.x;
    const int TOT = 2 * NSEQ * HSZ;
    if (idx >= TOT) return;
    g_c[idx] = c0[idx];
    int k = idx & 255;
    int n = (idx >> 8) % NSEQ;
    int d = idx / (NSEQ * HSZ);
    float v = h0[idx];
    uint16_t hb, lb; split_bf(v, hb, lb);
    int mt = n >> 7, m = n & 127;
    memcpy(&g_Ah[0][d][mt][0][m][k], &hb, 2);
    memcpy(&g_Ah[0][d][mt][1][m][k], &lb, 2);
}

// ---------------- xg GEMM: xg[dir][t] = x_t @ Wih^T + bias (3-pass split) ----------------
// grid (8 nt, 40 mt, 60 = t*2+dir), K=128 in 2 chunks of 64
#define STAGE_SZ 65536
__global__ void __launch_bounds__(256, 1) xg_gemm(void) {
    extern __shared__ __align__(16) unsigned char smem[];
    const uint32_t sbase = smem_u32(smem);
    const int tid = threadIdx.x, wid = tid >> 5, lane = tid & 31;
    const int wm = wid & 3, wn = wid >> 2;
    const int nt = blockIdx.x, mt = blockIdx.y;
    const int t = blockIdx.z >> 1, dir = blockIdx.z & 1;

    const __nv_bfloat16* Ap = &g_Ax[t][mt][0][0][0];
    const __nv_bfloat16* Bp = &g_Bx[dir][nt][0][0][0];

    auto load_chunk = [&](int ck, int st) {
        const uint32_t stg = sbase + st * STAGE_SZ;
#pragma unroll
        for (int j = 0; j < 8; j++) {
            int id = tid + j * 256;
            int img = id >> 10, row = (id >> 3) & 127, ch = id & 7;
            cpa16(stg + img * 16384 + swz128(row, ch),
                  Ap + (size_t)img * 16384 + row * 128 + ck * 64 + ch * 8);
        }
#pragma unroll
        for (int j = 0; j < 8; j++) {
            int id = tid + j * 256;
            int img = id >> 10, row = (id >> 3) & 127, ch = id & 7;
            cpa16(stg + 32768 + img * 16384 + swz128(row, ch),
                  Bp + (size_t)img * 16384 + row * 128 + ck * 64 + ch * 8);
        }
    };

    float acc[2][8][4];
#pragma unroll
    for (int mi = 0; mi < 2; mi++)
#pragma unroll
        for (int nj = 0; nj < 8; nj++)
#pragma unroll
            for (int e = 0; e < 4; e++) acc[mi][nj][e] = 0.0f;

    load_chunk(0, 0); CP_COMMIT();
    load_chunk(1, 1); CP_COMMIT();

    for (int ck = 0; ck < 2; ck++) {
        if (ck < 1) CP_WAIT1(); else CP_WAIT0();
        __syncthreads();
        const uint32_t stg = sbase + (ck & 1) * STAGE_SZ;
        const uint32_t Ab0 = stg, Ab1 = stg + 16384;
        const uint32_t Bb0 = stg + 32768, Bb1 = stg + 49152;
#pragma unroll
        for (int ks = 0; ks < 4; ks++) {
            const int ac = 2 * ks + (lane >> 4);
            uint32_t ah[2][4], al[2][4], bh[4][4], bl[4][4];
#pragma unroll
            for (int fi = 0; fi < 2; fi++) {
                const int row = wm * 32 + fi * 16 + (lane & 15);
                const uint32_t off = swz128(row, ac);
                ldm_x4(ah[fi], Ab0 + off);
                ldm_x4(al[fi], Ab1 + off);
            }
#pragma unroll
            for (int gp = 0; gp < 4; gp++) {
                const int col = wn * 64 + gp * 16 + (lane & 15);
                const uint32_t off = swz128(col, ac);
                ldm_x4(bh[gp], Bb0 + off);
                ldm_x4(bl[gp], Bb1 + off);
            }
#pragma unroll
            for (int mi = 0; mi < 2; mi++)
#pragma unroll
                for (int gp = 0; gp < 4; gp++)
#pragma unroll
                    for (int sub = 0; sub < 2; sub++) {
                        float* d = acc[mi][gp * 2 + sub];
                        mma16816(d, ah[mi], bh[gp][sub], bh[gp][sub + 2]);
                        mma16816(d, ah[mi], bl[gp][sub], bl[gp][sub + 2]);
                        mma16816(d, al[mi], bh[gp][sub], bh[gp][sub + 2]);
                    }
        }
        __syncthreads();
    }

    // epilogue: add bias, store fp32 fragments
    float* xgp = g_xg + (((size_t)(dir * T_STEPS + t) * 40 + mt) * 128) * 1024 + nt * 128;
    const float* bias = &g_bias[dir][nt * 128];
#pragma unroll
    for (int mi = 0; mi < 2; mi++)
#pragma unroll
        for (int nj = 0; nj < 8; nj++) {
            const int r = wm * 32 + mi * 16 + (lane >> 2);
            const int c = wn * 64 + nj * 8 + (lane & 3) * 2;
            const float b0 = bias[c], b1 = bias[c + 1];
            float2 v0 = { acc[mi][nj][0] + b0, acc[mi][nj][1] + b1 };
            float2 v1 = { acc[mi][nj][2] + b0, acc[mi][nj][3] + b1 };
            *(float2*)&xgp[(size_t)r * 1024 + c] = v0;
            *(float2*)&xgp[(size_t)(r + 8) * 1024 + c] = v1;
        }
}

// ---------------- LSTM step: acc init from xg, K=256 h-GEMM, fused cell ----------------
#define SM_TOTAL (2 * STAGE_SZ)   // 131072; epilogue C (128x132 f32 = 67584B) overlays stage 0

__global__ void __launch_bounds__(256, 1) lstm_step_mma(int s) {
    extern __shared__ __align__(16) unsigned char smem[];
    const uint32_t sbase = smem_u32(smem);
    const int tid = threadIdx.x, wid = tid >> 5, lane = tid & 31;
    const int wm = wid & 3, wn = wid >> 2;
    const int nt = blockIdx.x, mt = blockIdx.y, dir = blockIdx.z;
    const int t = dir ? (T_STEPS - 1 - s) : s;
    const int par = s & 1;

    const __nv_bfloat16* Ap = &g_Ah[par][dir][mt][0][0][0];
    const __nv_bfloat16* Bp = &g_Bh[dir][nt][0][0][0];

    auto load_chunk = [&](int ck, int st) {
        const uint32_t stg = sbase + st * STAGE_SZ;
#pragma unroll
        for (int j = 0; j < 8; j++) {
            int id = tid + j * 256;
            int img = id >> 10, row = (id >> 3) & 127, ch = id & 7;
            cpa16(stg + img * 16384 + swz128(row, ch),
                  Ap + (size_t)img * 32768 + row * 256 + ck * 64 + ch * 8);
        }
#pragma unroll
        for (int j = 0; j < 8; j++) {
            int id = tid + j * 256;
            int img = id >> 10, row = (id >> 3) & 127, ch = id & 7;
            cpa16(stg + 32768 + img * 16384 + swz128(row, ch),
                  Bp + (size_t)img * 32768 + row * 256 + ck * 64 + ch * 8);
        }
    };

    load_chunk(0, 0); CP_COMMIT();
    load_chunk(1, 1); CP_COMMIT();

    // accumulator init from precomputed xg (+bias already folded)
    const float* xgp = g_xg + (((size_t)(dir * T_STEPS + t) * 40 + mt) * 128) * 1024 + nt * 128;
    float acc[2][8][4];
#pragma unroll
    for (int mi = 0; mi < 2; mi++)
#pragma unroll
        for (int nj = 0; nj < 8; nj++) {
            const int r = wm * 32 + mi * 16 + (lane >> 2);
            const int c = wn * 64 + nj * 8 + (lane & 3) * 2;
            float2 v0 = *(const float2*)&xgp[(size_t)r * 1024 + c];
            float2 v1 = *(const float2*)&xgp[(size_t)(r + 8) * 1024 + c];
            acc[mi][nj][0] = v0.x; acc[mi][nj][1] = v0.y;
            acc[mi][nj][2] = v1.x; acc[mi][nj][3] = v1.y;
        }

    for (int ck = 0; ck < 4; ck++) {
        if (ck < 3) CP_WAIT1(); else CP_WAIT0();
        __syncthreads();
        const uint32_t stg = sbase + (ck & 1) * STAGE_SZ;
        const uint32_t Ab0 = stg, Ab1 = stg + 16384;
        const uint32_t Bb0 = stg + 32768, Bb1 = stg + 49152;
#pragma unroll
        for (int ks = 0; ks < 4; ks++) {
            const int ac = 2 * ks + (lane >> 4);
            uint32_t ah[2][4], al[2][4], bh[4][4], bl[4][4];
#pragma unroll
            for (int fi = 0; fi < 2; fi++) {
                const int row = wm * 32 + fi * 16 + (lane & 15);
                const uint32_t off = swz128(row, ac);
                ldm_x4(ah[fi], Ab0 + off);
                ldm_x4(al[fi], Ab1 + off);
            }
#pragma unroll
            for (int gp = 0; gp < 4; gp++) {
                const int col = wn * 64 + gp * 16 + (lane & 15);
                const uint32_t off = swz128(col, ac);
                ldm_x4(bh[gp], Bb0 + off);
                ldm_x4(bl[gp], Bb1 + off);
            }
#pragma unroll
            for (int mi = 0; mi < 2; mi++)
#pragma unroll
                for (int gp = 0; gp < 4; gp++)
#pragma unroll
                    for (int sub = 0; sub < 2; sub++) {
                        float* d = acc[mi][gp * 2 + sub];
                        mma16816(d, ah[mi], bh[gp][sub], bh[gp][sub + 2]);
                        mma16816(d, ah[mi], bl[gp][sub], bl[gp][sub + 2]);
                        mma16816(d, al[mi], bh[gp][sub], bh[gp][sub + 2]);
                    }
        }
        __syncthreads();
        if (ck + 2 < 4) { load_chunk(ck + 2, ck & 1); CP_COMMIT(); }
    }

    // ---------------- epilogue: gates -> smem -> LSTM cell (fast MUFU math) ----------------
    float* Csm = (float*)smem;
#pragma unroll
    for (int mi = 0; mi < 2; mi++)
#pragma unroll
        for (int nj = 0; nj < 8; nj++) {
            const int r = wm * 32 + mi * 16 + (lane >> 2);
            const int c = wn * 64 + nj * 8 + (lane & 3) * 2;
            float* p = Csm + r * 132 + c;
            p[0] = acc[mi][nj][0];
            p[1] = acc[mi][nj][1];
            float* q = Csm + (r + 8) * 132 + c;
            q[0] = acc[mi][nj][2];
            q[1] = acc[mi][nj][3];
        }
    __syncthreads();

    const int n_l = tid >> 1;
    const int halfh = tid & 1;
    const int n = mt * 128 + n_l;
    const size_t cbase = (size_t)dir * NSEQ * HSZ + (size_t)n * HSZ;
    uint16_t hb[16], lb[16];
#pragma unroll
    for (int i = 0; i < 16; i++) {
        const int h_l = halfh * 16 + i;
        const float4 gt = *(const float4*)&Csm[n_l * 132 + h_l * 4];
        const float iv = fsigm(gt.x);
        const float fv = fsigm(gt.y);
        const float gv = ftanh(gt.z);
        const float ov = fsigm(gt.w);
        const size_t ci = cbase + nt * 32 + h_l;
        const float cn = fv * g_c[ci] + iv * gv;
        g_c[ci] = cn;
        const float hv = ov * ftanh(cn);
        if (s == T_STEPS - 1) g_h[ci] = hv;
        split_bf(hv, hb[i], lb[i]);
    }
    {
        const int kcol = nt * 32 + halfh * 16;
        uint4 u0, u1;
        uint32_t* w;
        w = (uint32_t*)&u0;
#pragma unroll
        for (int q = 0; q < 4; q++) w[q] = (uint32_t)hb[q * 2] | ((uint32_t)hb[q * 2 + 1] << 16);
        w = (uint32_t*)&u1;
#pragma unroll
        for (int q = 0; q < 4; q++) w[q] = (uint32_t)hb[8 + q * 2] | ((uint32_t)hb[8 + q * 2 + 1] << 16);
        *(uint4*)&g_Ah[par ^ 1][dir][mt][0][n_l][kcol]     = u0;
        *(uint4*)&g_Ah[par ^ 1][dir][mt][0][n_l][kcol + 8] = u1;
        w = (uint32_t*)&u0;
#pragma unroll
        for (int q = 0; q < 4; q++) w[q] = (uint32_t)lb[q * 2] | ((uint32_t)lb[q * 2 + 1] << 16);
        w = (uint32_t*)&u1;
#pragma unroll
        for (int q = 0; q < 4; q++) w[q] = (uint32_t)lb[8 + q * 2] | ((uint32_t)lb[8 + q * 2 + 1] << 16);
        *(uint4*)&g_Ah[par ^ 1][dir][mt][1][n_l][kcol]     = u0;
        *(uint4*)&g_Ah[par ^ 1][dir][mt][1][n_l][kcol + 8] = u1;
    }
}

// ---------------- head ----------------
__global__ __launch_bounds__(256) void head_kernel(
    const float* __restrict__ W1, const float* __restrict__ b1,
    const float* __restrict__ W2, const float* __restrict__ b2,
    float* __restrict__ out)
{
    __shared__ float fea[2560];
    __shared__ float zp[4][64];
    __shared__ float zz[64];
    __shared__ float lg[5];

    const int b = blockIdx.x;
    const int tid = threadIdx.x;
    const float* __restrict__ hF = g_h;
    const float* __restrict__ hB = g_h + NSEQ * HSZ;

    for (int i = tid; i < 2560; i += 256) {
        const int slot = i >> 8;
        const int mcol = i & 255;
        const int n = b * 10 + slot;
        const float v = (mcol < 128) ? hF[(size_t)n * HSZ + mcol] : hB[(size_t)n * HSZ + mcol];
        fea[i] = v;
        out[2560 + (size_t)b * 2560 + i] = v;
    }
    __syncthreads();

    const int j = tid & 63;
    const int p = tid >> 6;
    float sum = 0.0f;
    const int k0 = p * 640;
    for (int k = k0; k < k0 + 640; k++) sum += fea[k] * W1[(size_t)j * 2560 + k];
    zp[p][j] = sum;
    __syncthreads();
    if (tid < 64) zz[tid] = zp[0][tid] + zp[1][tid] + zp[2][tid] + zp[3][tid] + b1[tid];
    __syncthreads();

    if (tid < 5) {
        float ss = b2[tid];
        for (int k = 0; k < 64; k++) ss += zz[k] * W2[tid * 64 + k];
        lg[tid] = ss;
    }
    __syncthreads();
    if (tid == 0) {
        float mx = lg[0];
        for (int k = 1; k < 5; k++) mx = fmaxf(mx, lg[k]);
        float e[5], se = 0.0f;
        for (int k = 0; k < 5; k++) { e[k] = expf(lg[k] - mx); se += e[k]; }
        for (int k = 0; k < 5; k++) out[(size_t)b * 5 + k] = e[k] / se;
    }
}

extern "C" void kernel_launch(void* const* d_in, const int* in_sizes, int n_in,
                              void* d_out, int out_size) {
    const float* x     = (const float*)d_in[0];
    const float* h0    = (const float*)d_in[1];
    const float* c0    = (const float*)d_in[2];
    const float* Wih_f = (const float*)d_in[3];
    const float* Whh_f = (const float*)d_in[4];
    const float* bih_f = (const float*)d_in[5];
    const float* bhh_f = (const float*)d_in[6];
    const float* Wih_b = (const float*)d_in[7];
    const float* Whh_b = (const float*)d_in[8];
    const float* bih_b = (const float*)d_in[9];
    const float* bhh_b = (const float*)d_in[10];
    const float* W1    = (const float*)d_in[11];
    const float* b1    = (const float*)d_in[12];
    const float* W2    = (const float*)d_in[13];
    const float* b2    = (const float*)d_in[14];
    float* out = (float*)d_out;

    cudaFuncSetAttribute(xg_gemm, cudaFuncAttributeMaxDynamicSharedMemorySize, SM_TOTAL);
    cudaFuncSetAttribute(lstm_step_mma, cudaFuncAttributeMaxDynamicSharedMemorySize, SM_TOTAL);

    // launch order chosen so ncu (-s 5 -c 1) lands on lstm_step_mma (launch #5)
    prepack_bias<<<8, 256>>>(bih_f, bhh_f, bih_b, bhh_b);                       // 0
    prepack_W<<<(2 * 8 * 128 * 384 + 255) / 256, 256>>>(Wih_f, Whh_f, Wih_b, Whh_b); // 1
    prepack_x<<<(T_STEPS * NSEQ * 128 + 255) / 256, 256>>>(x);                  // 2
    prepack_h0c0<<<(2 * NSEQ * HSZ + 255) / 256, 256>>>(h0, c0);                // 3
    xg_gemm<<<dim3(8, 40, 60), 256, SM_TOTAL>>>();                              // 4

    dim3 grid(8, 40, 2);
    for (int s = 0; s < T_STEPS; s++) {                                         // 5..34
        lstm_step_mma<<<grid, 256, SM_TOTAL>>>(s);
    }
    head_kernel<<<NBATCH, 256>>>(W1, b1, W2, b2, out);
}

// round 7
// speedup vs baseline: 2.1508x; 1.0150x over previous
#include <cuda_runtime.h>
#include <cuda_bf16.h>
#include <cstdint>
#include <cstring>
#include <math.h>

// ---------------- problem constants ----------------
#define T_STEPS 30
#define ISZ     100
#define HSZ     256
#define NSEQ    5120
#define NBATCH  512

// ---------------- device scratch (allocation-free rule) ----------------
__device__ __nv_bfloat16 g_Ax[T_STEPS][40][2][128][128];   // [t][mt][img][row][k]  x, k pad 100->128
__device__ __nv_bfloat16 g_Ah[2][2][40][2][128][256];      // [par][dir][mt][img][row][k]
__device__ __nv_bfloat16 g_Bx[2][8][2][128][128];          // [dir][nt][img][c'][k]  Wih, gate-interleaved
__device__ __nv_bfloat16 g_Bh[2][8][2][128][256];          // [dir][nt][img][c'][k]  Whh
__device__ float g_bias[2][1024];                           // [dir][c'=h*4+g]
__device__ float g_c[2 * NSEQ * HSZ];
__device__ float g_h[2 * NSEQ * HSZ];                       // finals only (s==29)
__device__ float g_xg[(size_t)2 * T_STEPS * 40 * 128 * 1024]; // [dir][t][mt][row][c']

// ---------------- helpers ----------------
__device__ __forceinline__ uint32_t smem_u32(const void* p) {
    uint32_t a;
    asm("{ .reg .u64 t; cvta.to.shared.u64 t, %1; cvt.u32.u64 %0, t; }" : "=r"(a) : "l"(p));
    return a;
}
__device__ __forceinline__ void cpa16(uint32_t dst, const void* src) {
    asm volatile("cp.async.cg.shared.global [%0], [%1], 16;" :: "r"(dst), "l"(src));
}
#define CP_COMMIT() asm volatile("cp.async.commit_group;" ::: "memory")
#define CP_WAIT2()  asm volatile("cp.async.wait_group 2;" ::: "memory")
#define CP_WAIT1()  asm volatile("cp.async.wait_group 1;" ::: "memory")
#define CP_WAIT0()  asm volatile("cp.async.wait_group 0;" ::: "memory")

__device__ __forceinline__ void ldm_x4(uint32_t* r, uint32_t addr) {
    asm volatile("ldmatrix.sync.aligned.m8n8.x4.shared.b16 {%0,%1,%2,%3}, [%4];"
                 : "=r"(r[0]), "=r"(r[1]), "=r"(r[2]), "=r"(r[3]) : "r"(addr));
}
__device__ __forceinline__ void mma16816(float* d, const uint32_t* a, uint32_t b0, uint32_t b1) {
    asm volatile(
        "mma.sync.aligned.m16n8k16.row.col.f32.bf16.bf16.f32 "
        "{%0,%1,%2,%3}, {%4,%5,%6,%7}, {%8,%9}, {%0,%1,%2,%3};"
        : "+f"(d[0]), "+f"(d[1]), "+f"(d[2]), "+f"(d[3])
        : "r"(a[0]), "r"(a[1]), "r"(a[2]), "r"(a[3]), "r"(b0), "r"(b1));
}
// 128B-row swizzle (8 x 16B chunks per row)
__device__ __forceinline__ uint32_t swz128(int row, int ch) {
    return (uint32_t)(row * 128 + ((ch ^ (row & 7)) << 4));
}
// 64B-row swizzle (4 x 16B chunks per row); conflict-free across 8-row ldmatrix phases
__device__ __forceinline__ uint32_t swz64(int row, int ch) {
    return (uint32_t)(row * 64 + ((ch ^ ((row >> 1) & 3)) << 4));
}
__device__ __forceinline__ float fsigm(float x) {
    float e;
    asm("ex2.approx.f32 %0, %1;" : "=f"(e) : "f"(x * -1.4426950408889634f));
    float r;
    asm("rcp.approx.f32 %0, %1;" : "=f"(r) : "f"(1.0f + e));
    return r;
}
__device__ __forceinline__ float ftanh(float x) { return fmaf(2.0f, fsigm(2.0f * x), -1.0f); }
__device__ __forceinline__ void split_bf(float v, uint16_t& hi_b, uint16_t& lo_b) {
    __nv_bfloat16 h = __float2bfloat16(v);
    float hf = __bfloat162float(h);
    memcpy(&hi_b, &h, 2);
    __nv_bfloat16 l = __float2bfloat16(v - hf);
    memcpy(&lo_b, &l, 2);
}

// ---------------- merged prepack (ONE launch) ----------------
#define SEG_BIAS 2048
#define SEG_W    (2 * 8 * 128 * 384)
#define SEG_X    (T_STEPS * NSEQ * 128)
#define SEG_HC   (2 * NSEQ * HSZ)
#define PRE_TOT  (SEG_BIAS + SEG_W + SEG_X + SEG_HC)

__global__ void prepack_all(const float* __restrict__ x,
                            const float* __restrict__ h0, const float* __restrict__ c0,
                            const float* __restrict__ Wih_f, const float* __restrict__ Whh_f,
                            const float* __restrict__ bih_f, const float* __restrict__ bhh_f,
                            const float* __restrict__ Wih_b, const float* __restrict__ Whh_b,
                            const float* __restrict__ bih_b, const float* __restrict__ bhh_b) {
    int idx = blockIdx.x * blockDim.x + threadIdx.x;
    if (idx < SEG_BIAS) {
        int c = idx & 1023, dir = idx >> 10;
        int h = c >> 2, g = c & 3;
        int row = g * HSZ + h;
        g_bias[dir][c] = dir ? (bih_b[row] + bhh_b[row]) : (bih_f[row] + bhh_f[row]);
        return;
    }
    idx -= SEG_BIAS;
    if (idx < SEG_W) {
        int k = idx % 384;
        int rest = idx / 384;
        int c = rest & 127;
        rest >>= 7;
        int nt = rest & 7;
        int dir = rest >> 3;
        const float* Wih = dir ? Wih_b : Wih_f;
        const float* Whh = dir ? Whh_b : Whh_f;
        int hg = nt * 32 + (c >> 2);
        int g = c & 3;
        int row = g * HSZ + hg;
        uint16_t hb, lb;
        if (k < 128) {
            float v = (k < ISZ) ? Wih[(size_t)row * ISZ + k] : 0.0f;
            split_bf(v, hb, lb);
            memcpy(&g_Bx[dir][nt][0][c][k], &hb, 2);
            memcpy(&g_Bx[dir][nt][1][c][k], &lb, 2);
        } else {
            float v = Whh[(size_t)row * HSZ + (k - 128)];
            split_bf(v, hb, lb);
            memcpy(&g_Bh[dir][nt][0][c][k - 128], &hb, 2);
            memcpy(&g_Bh[dir][nt][1][c][k - 128], &lb, 2);
        }
        return;
    }
    idx -= SEG_W;
    if (idx < SEG_X) {
        int k = idx & 127;
        int n = (idx >> 7) % NSEQ;
        int t = idx / (NSEQ * 128);
        float v = (k < ISZ) ? x[((size_t)n * T_STEPS + t) * ISZ + k] : 0.0f;
        uint16_t hb, lb; split_bf(v, hb, lb);
        int mt = n >> 7, m = n & 127;
        memcpy(&g_Ax[t][mt][0][m][k], &hb, 2);
        memcpy(&g_Ax[t][mt][1][m][k], &lb, 2);
        return;
    }
    idx -= SEG_X;
    if (idx < SEG_HC) {
        g_c[idx] = c0[idx];
        int k = idx & 255;
        int n = (idx >> 8) % NSEQ;
        int d = idx / (NSEQ * HSZ);
        float v = h0[idx];
        uint16_t hb, lb; split_bf(v, hb, lb);
        int mt = n >> 7, m = n & 127;
        memcpy(&g_Ah[0][d][mt][0][m][k], &hb, 2);
        memcpy(&g_Ah[0][d][mt][1][m][k], &lb, 2);
    }
}

// ---------------- persistent xg GEMM: B-resident, loop over all t ----------------
// smem: B resident 64KB [img][kh] @0 | A stages 2 x 64KB @65536
#define XG_SMEM (65536 + 2 * 65536)     // 196608

__global__ void __launch_bounds__(256, 1) xg_gemm(void) {
    extern __shared__ __align__(16) unsigned char smem[];
    const uint32_t sbase = smem_u32(smem);
    const int tid = threadIdx.x, wid = tid >> 5, lane = tid & 31;
    const int wm = wid & 3, wn = wid >> 2;
    const int nt = blockIdx.x, mt = blockIdx.y, dir = blockIdx.z;

    // bias -> regs (16 values per thread)
    float breg[8][2];
#pragma unroll
    for (int nj = 0; nj < 8; nj++) {
        const int c = wn * 64 + nj * 8 + (lane & 3) * 2;
        breg[nj][0] = g_bias[dir][nt * 128 + c];
        breg[nj][1] = g_bias[dir][nt * 128 + c + 1];
    }

    // load resident B (64KB): [img][kh][row 128][64k]
    {
        const __nv_bfloat16* Bp = &g_Bx[dir][nt][0][0][0];
#pragma unroll
        for (int j = 0; j < 16; j++) {
            int id = tid + j * 256;
            int img = id >> 11, kh = (id >> 10) & 1, row = (id >> 3) & 127, ch = id & 7;
            cpa16(sbase + img * 32768 + kh * 16384 + swz128(row, ch),
                  &Bp[(size_t)img * 16384 + row * 128 + kh * 64 + ch * 8]);
        }
    }
    CP_COMMIT();

    auto loadA = [&](int t, int st) {
        const __nv_bfloat16* Ap = &g_Ax[t][mt][0][0][0];
        const uint32_t astg = sbase + 65536 + st * 65536;
#pragma unroll
        for (int j = 0; j < 16; j++) {
            int id = tid + j * 256;
            int img = id >> 11, kh = (id >> 10) & 1, row = (id >> 3) & 127, ch = id & 7;
            cpa16(astg + img * 32768 + kh * 16384 + swz128(row, ch),
                  &Ap[(size_t)img * 16384 + row * 128 + kh * 64 + ch * 8]);
        }
    };
    loadA(0, 0);
    CP_COMMIT();

    for (int t = 0; t < T_STEPS; t++) {
        __syncthreads();                    // all warps done reading stage being overwritten
        if (t + 1 < T_STEPS) {
            loadA(t + 1, (t + 1) & 1);
            CP_COMMIT();
            CP_WAIT1();
        } else {
            CP_WAIT0();
        }
        __syncthreads();                    // data visible to all warps

        float acc[2][8][4];
#pragma unroll
        for (int mi = 0; mi < 2; mi++)
#pragma unroll
            for (int nj = 0; nj < 8; nj++)
#pragma unroll
                for (int e = 0; e < 4; e++) acc[mi][nj][e] = 0.0f;

        const uint32_t astg = sbase + 65536 + (t & 1) * 65536;
#pragma unroll
        for (int kh = 0; kh < 2; kh++) {
            const uint32_t Ab0 = astg + kh * 16384;
            const uint32_t Ab1 = astg + 32768 + kh * 16384;
            const uint32_t Bb0 = sbase + kh * 16384;
            const uint32_t Bb1 = sbase + 32768 + kh * 16384;
#pragma unroll
            for (int ks = 0; ks < 4; ks++) {
                const int ac = 2 * ks + (lane >> 4);
                uint32_t ah[2][4], al[2][4], bh[4][4], bl[4][4];
#pragma unroll
                for (int fi = 0; fi < 2; fi++) {
                    const int row = wm * 32 + fi * 16 + (lane & 15);
                    const uint32_t off = swz128(row, ac);
                    ldm_x4(ah[fi], Ab0 + off);
                    ldm_x4(al[fi], Ab1 + off);
                }
#pragma unroll
                for (int gp = 0; gp < 4; gp++) {
                    const int col = wn * 64 + gp * 16 + (lane & 15);
                    const uint32_t off = swz128(col, ac);
                    ldm_x4(bh[gp], Bb0 + off);
                    ldm_x4(bl[gp], Bb1 + off);
                }
#pragma unroll
                for (int mi = 0; mi < 2; mi++)
#pragma unroll
                    for (int gp = 0; gp < 4; gp++)
#pragma unroll
                        for (int sub = 0; sub < 2; sub++) {
                            float* d = acc[mi][gp * 2 + sub];
                            mma16816(d, ah[mi], bh[gp][sub], bh[gp][sub + 2]);
                            mma16816(d, ah[mi], bl[gp][sub], bl[gp][sub + 2]);
                            mma16816(d, al[mi], bh[gp][sub], bh[gp][sub + 2]);
                        }
            }
        }

        // epilogue: bias + store fp32
        float* xgp = g_xg + (((size_t)(dir * T_STEPS + t) * 40 + mt) * 128) * 1024 + nt * 128;
#pragma unroll
        for (int mi = 0; mi < 2; mi++)
#pragma unroll
            for (int nj = 0; nj < 8; nj++) {
                const int r = wm * 32 + mi * 16 + (lane >> 2);
                const int c = wn * 64 + nj * 8 + (lane & 3) * 2;
                float2 v0 = { acc[mi][nj][0] + breg[nj][0], acc[mi][nj][1] + breg[nj][1] };
                float2 v1 = { acc[mi][nj][2] + breg[nj][0], acc[mi][nj][3] + breg[nj][1] };
                *(float2*)&xgp[(size_t)r * 1024 + c] = v0;
                *(float2*)&xgp[(size_t)(r + 8) * 1024 + c] = v1;
            }
    }
}

// ---------------- LSTM step: K=256 over 8 chunks of 32, 4-stage pipeline ----------------
// stage 32KB: Aimg0 8K | Aimg1 8K | Bimg0 8K | Bimg1 8K; 4 stages = 128KB.
// epilogue Csm (128x132 f32 = 67.5KB) overlays stages.
#define ST_SZ    32768
#define SM_TOTAL (4 * ST_SZ)

__global__ void __launch_bounds__(256, 1) lstm_step_mma(int s) {
    extern __shared__ __align__(16) unsigned char smem[];
    const uint32_t sbase = smem_u32(smem);
    const int tid = threadIdx.x, wid = tid >> 5, lane = tid & 31;
    const int wm = wid & 3, wn = wid >> 2;
    const int nt = blockIdx.x, mt = blockIdx.y, dir = blockIdx.z;
    const int t = dir ? (T_STEPS - 1 - s) : s;
    const int par = s & 1;

    const __nv_bfloat16* Ap = &g_Ah[par][dir][mt][0][0][0];
    const __nv_bfloat16* Bp = &g_Bh[dir][nt][0][0][0];

    auto load_chunk = [&](int ck) {
        const uint32_t stg = sbase + (ck & 3) * ST_SZ;
#pragma unroll
        for (int j = 0; j < 4; j++) {
            int id = tid + j * 256;
            int img = id >> 9, row = (id >> 2) & 127, ch = id & 3;
            cpa16(stg + img * 8192 + swz64(row, ch),
                  &Ap[(size_t)img * 32768 + row * 256 + ck * 32 + ch * 8]);
        }
#pragma unroll
        for (int j = 0; j < 4; j++) {
            int id = tid + j * 256;
            int img = id >> 9, row = (id >> 2) & 127, ch = id & 3;
            cpa16(stg + 16384 + img * 8192 + swz64(row, ch),
                  &Bp[(size_t)img * 32768 + row * 256 + ck * 32 + ch * 8]);
        }
    };

    load_chunk(0); CP_COMMIT();
    load_chunk(1); CP_COMMIT();
    load_chunk(2); CP_COMMIT();

    // accumulator init from precomputed xg (+bias folded)
    const float* xgp = g_xg + (((size_t)(dir * T_STEPS + t) * 40 + mt) * 128) * 1024 + nt * 128;
    float acc[2][8][4];
#pragma unroll
    for (int mi = 0; mi < 2; mi++)
#pragma unroll
        for (int nj = 0; nj < 8; nj++) {
            const int r = wm * 32 + mi * 16 + (lane >> 2);
            const int c = wn * 64 + nj * 8 + (lane & 3) * 2;
            float2 v0 = *(const float2*)&xgp[(size_t)r * 1024 + c];
            float2 v1 = *(const float2*)&xgp[(size_t)(r + 8) * 1024 + c];
            acc[mi][nj][0] = v0.x; acc[mi][nj][1] = v0.y;
            acc[mi][nj][2] = v1.x; acc[mi][nj][3] = v1.y;
        }

    for (int ck = 0; ck < 8; ck++) {
        if (ck <= 5)      CP_WAIT2();
        else if (ck == 6) CP_WAIT1();
        else              CP_WAIT0();
        __syncthreads();
        if (ck + 3 < 8) { load_chunk(ck + 3); CP_COMMIT(); }

        const uint32_t stg = sbase + (ck & 3) * ST_SZ;
        const uint32_t Ab0 = stg, Ab1 = stg + 8192;
        const uint32_t Bb0 = stg + 16384, Bb1 = stg + 24576;
#pragma unroll
        for (int ks = 0; ks < 2; ks++) {
            const int ac = 2 * ks + (lane >> 4);
            uint32_t ah[2][4], al[2][4], bh[4][4], bl[4][4];
#pragma unroll
            for (int fi = 0; fi < 2; fi++) {
                const int row = wm * 32 + fi * 16 + (lane & 15);
                const uint32_t off = swz64(row, ac);
                ldm_x4(ah[fi], Ab0 + off);
                ldm_x4(al[fi], Ab1 + off);
            }
#pragma unroll
            for (int gp = 0; gp < 4; gp++) {
                const int col = wn * 64 + gp * 16 + (lane & 15);
                const uint32_t off = swz64(col, ac);
                ldm_x4(bh[gp], Bb0 + off);
                ldm_x4(bl[gp], Bb1 + off);
            }
#pragma unroll
            for (int mi = 0; mi < 2; mi++)
#pragma unroll
                for (int gp = 0; gp < 4; gp++)
#pragma unroll
                    for (int sub = 0; sub < 2; sub++) {
                        float* d = acc[mi][gp * 2 + sub];
                        mma16816(d, ah[mi], bh[gp][sub], bh[gp][sub + 2]);
                        mma16816(d, ah[mi], bl[gp][sub], bl[gp][sub + 2]);
                        mma16816(d, al[mi], bh[gp][sub], bh[gp][sub + 2]);
                    }
        }
    }
    __syncthreads();

    // ---------------- epilogue: gates -> smem -> LSTM cell ----------------
    float* Csm = (float*)smem;
#pragma unroll
    for (int mi = 0; mi < 2; mi++)
#pragma unroll
        for (int nj = 0; nj < 8; nj++) {
            const int r = wm * 32 + mi * 16 + (lane >> 2);
            const int c = wn * 64 + nj * 8 + (lane & 3) * 2;
            float* p = Csm + r * 132 + c;
            p[0] = acc[mi][nj][0];
            p[1] = acc[mi][nj][1];
            float* q = Csm + (r + 8) * 132 + c;
            q[0] = acc[mi][nj][2];
            q[1] = acc[mi][nj][3];
        }
    __syncthreads();

    const int n_l = tid >> 1;
    const int halfh = tid & 1;
    const int n = mt * 128 + n_l;
    const size_t cbase = (size_t)dir * NSEQ * HSZ + (size_t)n * HSZ;
    uint16_t hb[16], lb[16];
#pragma unroll
    for (int i = 0; i < 16; i++) {
        const int h_l = halfh * 16 + i;
        const float4 gt = *(const float4*)&Csm[n_l * 132 + h_l * 4];
        const float iv = fsigm(gt.x);
        const float fv = fsigm(gt.y);
        const float gv = ftanh(gt.z);
        const float ov = fsigm(gt.w);
        const size_t ci = cbase + nt * 32 + h_l;
        const float cn = fv * g_c[ci] + iv * gv;
        g_c[ci] = cn;
        const float hv = ov * ftanh(cn);
        if (s == T_STEPS - 1) g_h[ci] = hv;
        split_bf(hv, hb[i], lb[i]);
    }
    {
        const int kcol = nt * 32 + halfh * 16;
        uint4 u0, u1;
        uint32_t* w;
        w = (uint32_t*)&u0;
#pragma unroll
        for (int q = 0; q < 4; q++) w[q] = (uint32_t)hb[q * 2] | ((uint32_t)hb[q * 2 + 1] << 16);
        w = (uint32_t*)&u1;
#pragma unroll
        for (int q = 0; q < 4; q++) w[q] = (uint32_t)hb[8 + q * 2] | ((uint32_t)hb[8 + q * 2 + 1] << 16);
        *(uint4*)&g_Ah[par ^ 1][dir][mt][0][n_l][kcol]     = u0;
        *(uint4*)&g_Ah[par ^ 1][dir][mt][0][n_l][kcol + 8] = u1;
        w = (uint32_t*)&u0;
#pragma unroll
        for (int q = 0; q < 4; q++) w[q] = (uint32_t)lb[q * 2] | ((uint32_t)lb[q * 2 + 1] << 16);
        w = (uint32_t*)&u1;
#pragma unroll
        for (int q = 0; q < 4; q++) w[q] = (uint32_t)lb[8 + q * 2] | ((uint32_t)lb[8 + q * 2 + 1] << 16);
        *(uint4*)&g_Ah[par ^ 1][dir][mt][1][n_l][kcol]     = u0;
        *(uint4*)&g_Ah[par ^ 1][dir][mt][1][n_l][kcol + 8] = u1;
    }
}

// ---------------- head ----------------
__global__ __launch_bounds__(256) void head_kernel(
    const float* __restrict__ W1, const float* __restrict__ b1,
    const float* __restrict__ W2, const float* __restrict__ b2,
    float* __restrict__ out)
{
    __shared__ float fea[2560];
    __shared__ float zp[4][64];
    __shared__ float zz[64];
    __shared__ float lg[5];

    const int b = blockIdx.x;
    const int tid = threadIdx.x;
    const float* __restrict__ hF = g_h;
    const float* __restrict__ hB = g_h + NSEQ * HSZ;

    for (int i = tid; i < 2560; i += 256) {
        const int slot = i >> 8;
        const int mcol = i & 255;
        const int n = b * 10 + slot;
        const float v = (mcol < 128) ? hF[(size_t)n * HSZ + mcol] : hB[(size_t)n * HSZ + mcol];
        fea[i] = v;
        out[2560 + (size_t)b * 2560 + i] = v;
    }
    __syncthreads();

    const int j = tid & 63;
    const int p = tid >> 6;
    float sum = 0.0f;
    const int k0 = p * 640;
    for (int k = k0; k < k0 + 640; k++) sum += fea[k] * W1[(size_t)j * 2560 + k];
    zp[p][j] = sum;
    __syncthreads();
    if (tid < 64) zz[tid] = zp[0][tid] + zp[1][tid] + zp[2][tid] + zp[3][tid] + b1[tid];
    __syncthreads();

    if (tid < 5) {
        float ss = b2[tid];
        for (int k = 0; k < 64; k++) ss += zz[k] * W2[tid * 64 + k];
        lg[tid] = ss;
    }
    __syncthreads();
    if (tid == 0) {
        float mx = lg[0];
        for (int k = 1; k < 5; k++) mx = fmaxf(mx, lg[k]);
        float e[5], se = 0.0f;
        for (int k = 0; k < 5; k++) { e[k] = expf(lg[k] - mx); se += e[k]; }
        for (int k = 0; k < 5; k++) out[(size_t)b * 5 + k] = e[k] / se;
    }
}

extern "C" void kernel_launch(void* const* d_in, const int* in_sizes, int n_in,
                              void* d_out, int out_size) {
    const float* x     = (const float*)d_in[0];
    const float* h0    = (const float*)d_in[1];
    const float* c0    = (const float*)d_in[2];
    const float* Wih_f = (const float*)d_in[3];
    const float* Whh_f = (const float*)d_in[4];
    const float* bih_f = (const float*)d_in[5];
    const float* bhh_f = (const float*)d_in[6];
    const float* Wih_b = (const float*)d_in[7];
    const float* Whh_b = (const float*)d_in[8];
    const float* bih_b = (const float*)d_in[9];
    const float* bhh_b = (const float*)d_in[10];
    const float* W1    = (const float*)d_in[11];
    const float* b1    = (const float*)d_in[12];
    const float* W2    = (const float*)d_in[13];
    const float* b2    = (const float*)d_in[14];
    float* out = (float*)d_out;

    cudaFuncSetAttribute(xg_gemm, cudaFuncAttributeMaxDynamicSharedMemorySize, XG_SMEM);
    cudaFuncSetAttribute(lstm_step_mma, cudaFuncAttributeMaxDynamicSharedMemorySize, SM_TOTAL);

    // launches: 0 prepack, 1 xg, 2.. steps -> ncu sample lands on a step
    prepack_all<<<(PRE_TOT + 255) / 256, 256>>>(x, h0, c0, Wih_f, Whh_f, bih_f, bhh_f,
                                                Wih_b, Whh_b, bih_b, bhh_b);
    xg_gemm<<<dim3(8, 40, 2), 256, XG_SMEM>>>();

    dim3 grid(8, 40, 2);
    for (int s = 0; s < T_STEPS; s++) {
        lstm_step_mma<<<grid, 256, SM_TOTAL>>>(s);
    }
    head_kernel<<<NBATCH, 256>>>(W1, b1, W2, b2, out);
}

// round 8
// speedup vs baseline: 2.4838x; 1.1548x over previous
#include <cuda_runtime.h>
#include <cuda_bf16.h>
#include <cstdint>
#include <cstring>
#include <math.h>

// ---------------- problem constants ----------------
#define T_STEPS 30
#define ISZ     100
#define HSZ     256
#define NSEQ    5120
#define NBATCH  512

// ---------------- device scratch (allocation-free rule) ----------------
__device__ __nv_bfloat16 g_Ax[T_STEPS][40][2][128][128];   // [t][mt][img][row][k]  x, k pad 100->128
__device__ __nv_bfloat16 g_Ah[2][2][40][2][128][256];      // [par][dir][mt][img][row][k]
__device__ __nv_bfloat16 g_Bx[2][8][2][128][128];          // [dir][nt8][img][c'][k]  Wih, gate-interleaved
__device__ __nv_bfloat16 g_Bh[2][8][2][128][256];          // [dir][nt8][img][c'][k]  Whh
__device__ float g_bias[2][1024];                           // [dir][c'=h*4+g]
__device__ float g_c[2 * NSEQ * HSZ];
__device__ float g_h[2 * NSEQ * HSZ];                       // finals only (s==29)
__device__ float g_xg[(size_t)2 * T_STEPS * 40 * 128 * 1024]; // [dir][t][mt][row][c']

// ---------------- helpers ----------------
__device__ __forceinline__ uint32_t smem_u32(const void* p) {
    uint32_t a;
    asm("{ .reg .u64 t; cvta.to.shared.u64 t, %1; cvt.u32.u64 %0, t; }" : "=r"(a) : "l"(p));
    return a;
}
__device__ __forceinline__ void cpa16(uint32_t dst, const void* src) {
    asm volatile("cp.async.cg.shared.global [%0], [%1], 16;" :: "r"(dst), "l"(src));
}
#define CP_COMMIT() asm volatile("cp.async.commit_group;" ::: "memory")
#define CP_WAIT1()  asm volatile("cp.async.wait_group 1;" ::: "memory")
#define CP_WAIT0()  asm volatile("cp.async.wait_group 0;" ::: "memory")

__device__ __forceinline__ void ldm_x4(uint32_t* r, uint32_t addr) {
    asm volatile("ldmatrix.sync.aligned.m8n8.x4.shared.b16 {%0,%1,%2,%3}, [%4];"
                 : "=r"(r[0]), "=r"(r[1]), "=r"(r[2]), "=r"(r[3]) : "r"(addr));
}
__device__ __forceinline__ void mma16816(float* d, const uint32_t* a, uint32_t b0, uint32_t b1) {
    asm volatile(
        "mma.sync.aligned.m16n8k16.row.col.f32.bf16.bf16.f32 "
        "{%0,%1,%2,%3}, {%4,%5,%6,%7}, {%8,%9}, {%0,%1,%2,%3};"
        : "+f"(d[0]), "+f"(d[1]), "+f"(d[2]), "+f"(d[3])
        : "r"(a[0]), "r"(a[1]), "r"(a[2]), "r"(a[3]), "r"(b0), "r"(b1));
}
// 128B-row swizzle (8 x 16B chunks per row)
__device__ __forceinline__ uint32_t swz128(int row, int ch) {
    return (uint32_t)(row * 128 + ((ch ^ (row & 7)) << 4));
}
// 64B-row swizzle (4 x 16B chunks per row)
__device__ __forceinline__ uint32_t swz64(int row, int ch) {
    return (uint32_t)(row * 64 + ((ch ^ ((row >> 1) & 3)) << 4));
}
__device__ __forceinline__ float fsigm(float x) {
    float e;
    asm("ex2.approx.f32 %0, %1;" : "=f"(e) : "f"(x * -1.4426950408889634f));
    float r;
    asm("rcp.approx.f32 %0, %1;" : "=f"(r) : "f"(1.0f + e));
    return r;
}
__device__ __forceinline__ float ftanh(float x) { return fmaf(2.0f, fsigm(2.0f * x), -1.0f); }
__device__ __forceinline__ void split_bf(float v, uint16_t& hi_b, uint16_t& lo_b) {
    __nv_bfloat16 h = __float2bfloat16(v);
    float hf = __bfloat162float(h);
    memcpy(&hi_b, &h, 2);
    __nv_bfloat16 l = __float2bfloat16(v - hf);
    memcpy(&lo_b, &l, 2);
}

// ---------------- merged prepack (ONE launch) ----------------
#define SEG_BIAS 2048
#define SEG_W    (2 * 8 * 128 * 384)
#define SEG_X    (T_STEPS * NSEQ * 128)
#define SEG_HC   (2 * NSEQ * HSZ)
#define PRE_TOT  (SEG_BIAS + SEG_W + SEG_X + SEG_HC)

__global__ void prepack_all(const float* __restrict__ x,
                            const float* __restrict__ h0, const float* __restrict__ c0,
                            const float* __restrict__ Wih_f, const float* __restrict__ Whh_f,
                            const float* __restrict__ bih_f, const float* __restrict__ bhh_f,
                            const float* __restrict__ Wih_b, const float* __restrict__ Whh_b,
                            const float* __restrict__ bih_b, const float* __restrict__ bhh_b) {
    int idx = blockIdx.x * blockDim.x + threadIdx.x;
    if (idx < SEG_BIAS) {
        int c = idx & 1023, dir = idx >> 10;
        int h = c >> 2, g = c & 3;
        int row = g * HSZ + h;
        g_bias[dir][c] = dir ? (bih_b[row] + bhh_b[row]) : (bih_f[row] + bhh_f[row]);
        return;
    }
    idx -= SEG_BIAS;
    if (idx < SEG_W) {
        int k = idx % 384;
        int rest = idx / 384;
        int c = rest & 127;
        rest >>= 7;
        int nt = rest & 7;
        int dir = rest >> 3;
        const float* Wih = dir ? Wih_b : Wih_f;
        const float* Whh = dir ? Whh_b : Whh_f;
        int hg = nt * 32 + (c >> 2);
        int g = c & 3;
        int row = g * HSZ + hg;
        uint16_t hb, lb;
        if (k < 128) {
            float v = (k < ISZ) ? Wih[(size_t)row * ISZ + k] : 0.0f;
            split_bf(v, hb, lb);
            memcpy(&g_Bx[dir][nt][0][c][k], &hb, 2);
            memcpy(&g_Bx[dir][nt][1][c][k], &lb, 2);
        } else {
            float v = Whh[(size_t)row * HSZ + (k - 128)];
            split_bf(v, hb, lb);
            memcpy(&g_Bh[dir][nt][0][c][k - 128], &hb, 2);
            memcpy(&g_Bh[dir][nt][1][c][k - 128], &lb, 2);
        }
        return;
    }
    idx -= SEG_W;
    if (idx < SEG_X) {
        int k = idx & 127;
        int n = (idx >> 7) % NSEQ;
        int t = idx / (NSEQ * 128);
        float v = (k < ISZ) ? x[((size_t)n * T_STEPS + t) * ISZ + k] : 0.0f;
        uint16_t hb, lb; split_bf(v, hb, lb);
        int mt = n >> 7, m = n & 127;
        memcpy(&g_Ax[t][mt][0][m][k], &hb, 2);
        memcpy(&g_Ax[t][mt][1][m][k], &lb, 2);
        return;
    }
    idx -= SEG_X;
    if (idx < SEG_HC) {
        g_c[idx] = c0[idx];
        int k = idx & 255;
        int n = (idx >> 8) % NSEQ;
        int d = idx / (NSEQ * HSZ);
        float v = h0[idx];
        uint16_t hb, lb; split_bf(v, hb, lb);
        int mt = n >> 7, m = n & 127;
        memcpy(&g_Ah[0][d][mt][0][m][k], &hb, 2);
        memcpy(&g_Ah[0][d][mt][1][m][k], &lb, 2);
    }
}

// ---------------- xg GEMM v2: N=64 tiles, B-resident 32KB, 2 CTAs/SM ----------------
// smem: B resident 32KB [(kh*2+img)*8192] @0 | A stages 2 x 32KB @32768 ([img][row128][k64])
#define XG_SMEM (32768 + 2 * 32768)   // 98304

__global__ void __launch_bounds__(256, 2) xg_gemm(void) {
    extern __shared__ __align__(16) unsigned char smem[];
    const uint32_t sbase = smem_u32(smem);
    const int tid = threadIdx.x, wid = tid >> 5, lane = tid & 31;
    const int wm = wid & 3, wn = wid >> 2;   // warp tile: 32 rows x 32 cols
    const int nt = blockIdx.x;               // 16 tiles of 64 cols
    const int mt = blockIdx.y, dir = blockIdx.z;

    // bias -> regs
    float breg[4][2];
#pragma unroll
    for (int nj = 0; nj < 4; nj++) {
        const int c = wn * 32 + nj * 8 + (lane & 3) * 2;
        breg[nj][0] = g_bias[dir][nt * 64 + c];
        breg[nj][1] = g_bias[dir][nt * 64 + c + 1];
    }

    // load resident B (32KB): blocks (kh, img) of [c 64][k 64]
    {
#pragma unroll
        for (int j = 0; j < 8; j++) {
            int id = tid + j * 256;
            int kh = id >> 10, img = (id >> 9) & 1, row = (id >> 3) & 63, ch = id & 7;
            cpa16(sbase + (kh * 2 + img) * 8192 + swz128(row, ch),
                  &g_Bx[dir][nt >> 1][img][(nt & 1) * 64 + row][kh * 64 + ch * 8]);
        }
    }
    CP_COMMIT();

    auto loadA = [&](int q) {   // q = t*2 + kh
        const int t = q >> 1, kh = q & 1;
        const uint32_t astg = sbase + 32768 + (q & 1 ? 32768 : 0) * 0 + ((q & 1)) * 0 + ((q % 2)) * 0 + ((q & 1)) * 0 + ( (q & 1) ) * 0 + ((q>>0)&0); // placeholder
        (void)astg;
        const uint32_t stg = sbase + 32768 + (q & 1) * 32768;
#pragma unroll
        for (int j = 0; j < 8; j++) {
            int id = tid + j * 256;
            int img = id >> 10, row = (id >> 3) & 127, ch = id & 7;
            cpa16(stg + img * 16384 + swz128(row, ch),
                  &g_Ax[t][mt][img][row][kh * 64 + ch * 8]);
        }
    };
    loadA(0); CP_COMMIT();
    loadA(1); CP_COMMIT();

    float acc[2][4][4];
#pragma unroll
    for (int mi = 0; mi < 2; mi++)
#pragma unroll
        for (int nj = 0; nj < 4; nj++)
#pragma unroll
            for (int e = 0; e < 4; e++) acc[mi][nj][e] = 0.0f;

    for (int q = 0; q < 2 * T_STEPS; q++) {
        const int kh = q & 1;
        if (q < 2 * T_STEPS - 1) CP_WAIT1(); else CP_WAIT0();
        __syncthreads();

        const uint32_t astg = sbase + 32768 + (q & 1) * 32768;
        const uint32_t Ab0 = astg, Ab1 = astg + 16384;
        const uint32_t Bb0 = sbase + (kh * 2 + 0) * 8192;
        const uint32_t Bb1 = sbase + (kh * 2 + 1) * 8192;
#pragma unroll
        for (int ks = 0; ks < 4; ks++) {
            const int ac = 2 * ks + (lane >> 4);
            uint32_t ah[2][4], al[2][4], bh[2][4], bl[2][4];
#pragma unroll
            for (int fi = 0; fi < 2; fi++) {
                const int row = wm * 32 + fi * 16 + (lane & 15);
                const uint32_t off = swz128(row, ac);
                ldm_x4(ah[fi], Ab0 + off);
                ldm_x4(al[fi], Ab1 + off);
            }
#pragma unroll
            for (int gp = 0; gp < 2; gp++) {
                const int col = wn * 32 + gp * 16 + (lane & 15);
                const uint32_t off = swz128(col, ac);
                ldm_x4(bh[gp], Bb0 + off);
                ldm_x4(bl[gp], Bb1 + off);
            }
#pragma unroll
            for (int mi = 0; mi < 2; mi++)
#pragma unroll
                for (int gp = 0; gp < 2; gp++)
#pragma unroll
                    for (int sub = 0; sub < 2; sub++) {
                        float* d = acc[mi][gp * 2 + sub];
                        mma16816(d, ah[mi], bh[gp][sub], bh[gp][sub + 2]);
                        mma16816(d, ah[mi], bl[gp][sub], bl[gp][sub + 2]);
                        mma16816(d, al[mi], bh[gp][sub], bh[gp][sub + 2]);
                    }
        }
        __syncthreads();
        if (q + 2 < 2 * T_STEPS) { loadA(q + 2); CP_COMMIT(); }

        if (kh == 1) {
            // finished t = q>>1: store with bias, reset acc
            const int t = q >> 1;
            float* xgp = g_xg + (((size_t)(dir * T_STEPS + t) * 40 + mt) * 128) * 1024 + nt * 64;
#pragma unroll
            for (int mi = 0; mi < 2; mi++)
#pragma unroll
                for (int nj = 0; nj < 4; nj++) {
                    const int r = wm * 32 + mi * 16 + (lane >> 2);
                    const int c = wn * 32 + nj * 8 + (lane & 3) * 2;
                    float2 v0 = { acc[mi][nj][0] + breg[nj][0], acc[mi][nj][1] + breg[nj][1] };
                    float2 v1 = { acc[mi][nj][2] + breg[nj][0], acc[mi][nj][3] + breg[nj][1] };
                    *(float2*)&xgp[(size_t)r * 1024 + c] = v0;
                    *(float2*)&xgp[(size_t)(r + 8) * 1024 + c] = v1;
#pragma unroll
                    for (int e = 0; e < 4; e++) acc[mi][nj][e] = 0.0f;
                }
        }
    }
}

// ---------------- LSTM step: K=256 over 8 chunks of 32, 2-stage, 2 CTAs/SM ----------------
// stage 32KB: Aimg0 8K | Aimg1 8K | Bimg0 8K | Bimg1 8K; 2 stages = 64KB.
// epilogue C (128 x 132 f32 = 67584B) overlays stages -> smem high-water 67584.
#define ST_SZ    32768
#define SM_TOTAL 67584

__global__ void __launch_bounds__(256, 2) lstm_step_mma(int s) {
    extern __shared__ __align__(16) unsigned char smem[];
    const uint32_t sbase = smem_u32(smem);
    const int tid = threadIdx.x, wid = tid >> 5, lane = tid & 31;
    const int wm = wid & 3, wn = wid >> 2;
    const int nt = blockIdx.x, mt = blockIdx.y, dir = blockIdx.z;
    const int t = dir ? (T_STEPS - 1 - s) : s;
    const int par = s & 1;

    const __nv_bfloat16* Ap = &g_Ah[par][dir][mt][0][0][0];
    const __nv_bfloat16* Bp = &g_Bh[dir][nt][0][0][0];

    auto load_chunk = [&](int ck) {
        const uint32_t stg = sbase + (ck & 1) * ST_SZ;
#pragma unroll
        for (int j = 0; j < 4; j++) {
            int id = tid + j * 256;
            int img = id >> 9, row = (id >> 2) & 127, ch = id & 3;
            cpa16(stg + img * 8192 + swz64(row, ch),
                  &Ap[(size_t)img * 32768 + row * 256 + ck * 32 + ch * 8]);
        }
#pragma unroll
        for (int j = 0; j < 4; j++) {
            int id = tid + j * 256;
            int img = id >> 9, row = (id >> 2) & 127, ch = id & 3;
            cpa16(stg + 16384 + img * 8192 + swz64(row, ch),
                  &Bp[(size_t)img * 32768 + row * 256 + ck * 32 + ch * 8]);
        }
    };

    load_chunk(0); CP_COMMIT();
    load_chunk(1); CP_COMMIT();

    // accumulator init from precomputed xg (+bias folded)
    const float* xgp = g_xg + (((size_t)(dir * T_STEPS + t) * 40 + mt) * 128) * 1024 + nt * 128;
    float acc[2][8][4];
#pragma unroll
    for (int mi = 0; mi < 2; mi++)
#pragma unroll
        for (int nj = 0; nj < 8; nj++) {
            const int r = wm * 32 + mi * 16 + (lane >> 2);
            const int c = wn * 64 + nj * 8 + (lane & 3) * 2;
            float2 v0 = *(const float2*)&xgp[(size_t)r * 1024 + c];
            float2 v1 = *(const float2*)&xgp[(size_t)(r + 8) * 1024 + c];
            acc[mi][nj][0] = v0.x; acc[mi][nj][1] = v0.y;
            acc[mi][nj][2] = v1.x; acc[mi][nj][3] = v1.y;
        }

    for (int ck = 0; ck < 8; ck++) {
        if (ck < 7) CP_WAIT1(); else CP_WAIT0();
        __syncthreads();

        const uint32_t stg = sbase + (ck & 1) * ST_SZ;
        const uint32_t Ab0 = stg, Ab1 = stg + 8192;
        const uint32_t Bb0 = stg + 16384, Bb1 = stg + 24576;
#pragma unroll
        for (int ks = 0; ks < 2; ks++) {
            const int ac = 2 * ks + (lane >> 4);
            uint32_t ah[2][4], al[2][4];
#pragma unroll
            for (int fi = 0; fi < 2; fi++) {
                const int row = wm * 32 + fi * 16 + (lane & 15);
                const uint32_t off = swz64(row, ac);
                ldm_x4(ah[fi], Ab0 + off);
                ldm_x4(al[fi], Ab1 + off);
            }
#pragma unroll
            for (int gph = 0; gph < 2; gph++) {
                uint32_t bh2[2][4], bl2[2][4];
#pragma unroll
                for (int gi = 0; gi < 2; gi++) {
                    const int col = wn * 64 + (gph * 2 + gi) * 16 + (lane & 15);
                    const uint32_t off = swz64(col, ac);
                    ldm_x4(bh2[gi], Bb0 + off);
                    ldm_x4(bl2[gi], Bb1 + off);
                }
#pragma unroll
                for (int mi = 0; mi < 2; mi++)
#pragma unroll
                    for (int gi = 0; gi < 2; gi++)
#pragma unroll
                        for (int sub = 0; sub < 2; sub++) {
                            float* d = acc[mi][(gph * 2 + gi) * 2 + sub];
                            mma16816(d, ah[mi], bh2[gi][sub], bh2[gi][sub + 2]);
                            mma16816(d, ah[mi], bl2[gi][sub], bl2[gi][sub + 2]);
                            mma16816(d, al[mi], bh2[gi][sub], bh2[gi][sub + 2]);
                        }
            }
        }
        __syncthreads();
        if (ck + 2 < 8) { load_chunk(ck + 2); CP_COMMIT(); }
    }
    __syncthreads();

    // ---------------- epilogue: gates -> smem -> LSTM cell ----------------
    float* Csm = (float*)smem;
#pragma unroll
    for (int mi = 0; mi < 2; mi++)
#pragma unroll
        for (int nj = 0; nj < 8; nj++) {
            const int r = wm * 32 + mi * 16 + (lane >> 2);
            const int c = wn * 64 + nj * 8 + (lane & 3) * 2;
            float* p = Csm + r * 132 + c;
            p[0] = acc[mi][nj][0];
            p[1] = acc[mi][nj][1];
            float* q = Csm + (r + 8) * 132 + c;
            q[0] = acc[mi][nj][2];
            q[1] = acc[mi][nj][3];
        }
    __syncthreads();

    const int n_l = tid >> 1;
    const int halfh = tid & 1;
    const int n = mt * 128 + n_l;
    const size_t cbase = (size_t)dir * NSEQ * HSZ + (size_t)n * HSZ;
    uint16_t hb[16], lb[16];
#pragma unroll
    for (int i = 0; i < 16; i++) {
        const int h_l = halfh * 16 + i;
        const float4 gt = *(const float4*)&Csm[n_l * 132 + h_l * 4];
        const float iv = fsigm(gt.x);
        const float fv = fsigm(gt.y);
        const float gv = ftanh(gt.z);
        const float ov = fsigm(gt.w);
        const size_t ci = cbase + nt * 32 + h_l;
        const float cn = fv * g_c[ci] + iv * gv;
        g_c[ci] = cn;
        const float hv = ov * ftanh(cn);
        if (s == T_STEPS - 1) g_h[ci] = hv;
        split_bf(hv, hb[i], lb[i]);
    }
    {
        const int kcol = nt * 32 + halfh * 16;
        uint4 u0, u1;
        uint32_t* w;
        w = (uint32_t*)&u0;
#pragma unroll
        for (int q = 0; q < 4; q++) w[q] = (uint32_t)hb[q * 2] | ((uint32_t)hb[q * 2 + 1] << 16);
        w = (uint32_t*)&u1;
#pragma unroll
        for (int q = 0; q < 4; q++) w[q] = (uint32_t)hb[8 + q * 2] | ((uint32_t)hb[8 + q * 2 + 1] << 16);
        *(uint4*)&g_Ah[par ^ 1][dir][mt][0][n_l][kcol]     = u0;
        *(uint4*)&g_Ah[par ^ 1][dir][mt][0][n_l][kcol + 8] = u1;
        w = (uint32_t*)&u0;
#pragma unroll
        for (int q = 0; q < 4; q++) w[q] = (uint32_t)lb[q * 2] | ((uint32_t)lb[q * 2 + 1] << 16);
        w = (uint32_t*)&u1;
#pragma unroll
        for (int q = 0; q < 4; q++) w[q] = (uint32_t)lb[8 + q * 2] | ((uint32_t)lb[8 + q * 2 + 1] << 16);
        *(uint4*)&g_Ah[par ^ 1][dir][mt][1][n_l][kcol]     = u0;
        *(uint4*)&g_Ah[par ^ 1][dir][mt][1][n_l][kcol + 8] = u1;
    }
}

// ---------------- head ----------------
__global__ __launch_bounds__(256) void head_kernel(
    const float* __restrict__ W1, const float* __restrict__ b1,
    const float* __restrict__ W2, const float* __restrict__ b2,
    float* __restrict__ out)
{
    __shared__ float fea[2560];
    __shared__ float zp[4][64];
    __shared__ float zz[64];
    __shared__ float lg[5];

    const int b = blockIdx.x;
    const int tid = threadIdx.x;
    const float* __restrict__ hF = g_h;
    const float* __restrict__ hB = g_h + NSEQ * HSZ;

    for (int i = tid; i < 2560; i += 256) {
        const int slot = i >> 8;
        const int mcol = i & 255;
        const int n = b * 10 + slot;
        const float v = (mcol < 128) ? hF[(size_t)n * HSZ + mcol] : hB[(size_t)n * HSZ + mcol];
        fea[i] = v;
        out[2560 + (size_t)b * 2560 + i] = v;
    }
    __syncthreads();

    const int j = tid & 63;
    const int p = tid >> 6;
    float sum = 0.0f;
    const int k0 = p * 640;
    for (int k = k0; k < k0 + 640; k++) sum += fea[k] * W1[(size_t)j * 2560 + k];
    zp[p][j] = sum;
    __syncthreads();
    if (tid < 64) zz[tid] = zp[0][tid] + zp[1][tid] + zp[2][tid] + zp[3][tid] + b1[tid];
    __syncthreads();

    if (tid < 5) {
        float ss = b2[tid];
        for (int k = 0; k < 64; k++) ss += zz[k] * W2[tid * 64 + k];
        lg[tid] = ss;
    }
    __syncthreads();
    if (tid == 0) {
        float mx = lg[0];
        for (int k = 1; k < 5; k++) mx = fmaxf(mx, lg[k]);
        float e[5], se = 0.0f;
        for (int k = 0; k < 5; k++) { e[k] = expf(lg[k] - mx); se += e[k]; }
        for (int k = 0; k < 5; k++) out[(size_t)b * 5 + k] = e[k] / se;
    }
}

extern "C" void kernel_launch(void* const* d_in, const int* in_sizes, int n_in,
                              void* d_out, int out_size) {
    const float* x     = (const float*)d_in[0];
    const float* h0    = (const float*)d_in[1];
    const float* c0    = (const float*)d_in[2];
    const float* Wih_f = (const float*)d_in[3];
    const float* Whh_f = (const float*)d_in[4];
    const float* bih_f = (const float*)d_in[5];
    const float* bhh_f = (const float*)d_in[6];
    const float* Wih_b = (const float*)d_in[7];
    const float* Whh_b = (const float*)d_in[8];
    const float* bih_b = (const float*)d_in[9];
    const float* bhh_b = (const float*)d_in[10];
    const float* W1    = (const float*)d_in[11];
    const float* b1    = (const float*)d_in[12];
    const float* W2    = (const float*)d_in[13];
    const float* b2    = (const float*)d_in[14];
    float* out = (float*)d_out;

    cudaFuncSetAttribute(xg_gemm, cudaFuncAttributeMaxDynamicSharedMemorySize, XG_SMEM);
    cudaFuncSetAttribute(lstm_step_mma, cudaFuncAttributeMaxDynamicSharedMemorySize, SM_TOTAL);

    // launches: 0 prepack, 1 xg, 2.. steps -> ncu sample lands on a step
    prepack_all<<<(PRE_TOT + 255) / 256, 256>>>(x, h0, c0, Wih_f, Whh_f, bih_f, bhh_f,
                                                Wih_b, Whh_b, bih_b, bhh_b);
    xg_gemm<<<dim3(16, 40, 2), 256, XG_SMEM>>>();

    dim3 grid(8, 40, 2);
    for (int s = 0; s < T_STEPS; s++) {
        lstm_step_mma<<<grid, 256, SM_TOTAL>>>(s);
    }
    head_kernel<<<NBATCH, 256>>>(W1, b1, W2, b2, out);
}